// round 14
// baseline (speedup 1.0000x reference)
#include <cuda_runtime.h>
#include <cuda_fp16.h>
#include <cstdint>

#define T_TOK 4096
#define E_DIM 4096
#define B_SZ  4
#define S_LEN 1024
#define H_NUM 32
#define D_HEAD 128
#define BS_BLK 16
#define NB_BLK 64
#define QMAX 32500.0f

// Scratch (allocation-free rule: __device__ globals)
__device__ float  g_qkv[3ULL * T_TOK * E_DIM];        // q | k | v fp32
__device__ float  g_attn[(size_t)T_TOK * E_DIM];      // attention output fp32
__device__ int8_t g_w8h[4ULL * E_DIM * E_DIM];        // weight hi planes [4][N][K]
__device__ int8_t g_w8l[4ULL * E_DIM * E_DIM];        // weight lo planes
__device__ int8_t g_a8h[(size_t)T_TOK * E_DIM];       // activation hi plane
__device__ int8_t g_a8l[(size_t)T_TOK * E_DIM];       // activation lo plane
__device__ float  g_qa[T_TOK];                        // activation quant mult (QMAX/max)
__device__ float  g_ra[T_TOK];                        // activation dequant mult (max/QMAX)
__device__ float  g_qb[4 * E_DIM];                    // weight quant mult
__device__ float  g_rb[4 * E_DIM];                    // weight dequant mult

// ===========================================================================
// helpers
// ===========================================================================
__device__ __forceinline__ uint32_t smem_u32(const void* p) {
    uint32_t a;
    asm("{ .reg .u64 t; cvta.to.shared.u64 t, %1; cvt.u32.u64 %0, t; }" : "=r"(a) : "l"(p));
    return a;
}
__device__ __forceinline__ void cp16(uint32_t dst, const void* src) {
    asm volatile("cp.async.ca.shared.global [%0], [%1], 16;" :: "r"(dst), "l"(src));
}
#define CP_COMMIT() asm volatile("cp.async.commit_group;" ::: "memory")
#define CP_WAIT0()  asm volatile("cp.async.wait_group 0;" ::: "memory")

__device__ __forceinline__ void mma_s8(int* c, const uint32_t* a, const uint32_t* b) {
    asm volatile(
        "mma.sync.aligned.m16n8k32.row.col.s32.s8.s8.s32 "
        "{%0,%1,%2,%3}, {%4,%5,%6,%7}, {%8,%9}, {%0,%1,%2,%3};"
        : "+r"(c[0]), "+r"(c[1]), "+r"(c[2]), "+r"(c[3])
        : "r"(a[0]), "r"(a[1]), "r"(a[2]), "r"(a[3]), "r"(b[0]), "r"(b[1]));
}
__device__ __forceinline__ void ldmatrix_x4(uint32_t* r, uint32_t addr) {
    asm volatile("ldmatrix.sync.aligned.m8n8.x4.shared.b16 {%0,%1,%2,%3}, [%4];"
                 : "=r"(r[0]), "=r"(r[1]), "=r"(r[2]), "=r"(r[3]) : "r"(addr));
}

// Packed fp32x2 ops (Blackwell)
#define FMA2(acc, a, b) \
    asm("fma.rn.f32x2 %0, %1, %2, %0;" : "+l"(acc) : "l"(a), "l"(b))
#define MUL2(out, a, b) \
    asm("mul.rn.f32x2 %0, %1, %2;" : "=l"(out) : "l"(a), "l"(b))
#define PACK2(out, lo, hi) \
    asm("mov.b64 %0, {%1, %2};" : "=l"(out) : "f"(lo), "f"(hi))
#define UNPACK2(lo, hi, in) \
    asm("mov.b64 {%0, %1}, %2;" : "=f"(lo), "=f"(hi) : "l"(in))

// 16-bit fixed-point split into two s8 planes
__device__ __forceinline__ void quant16(float x, float q, int8_t& hi, int8_t& lo) {
    int v = __float2int_rn(x * q);
    v = max(-32500, min(32500, v));
    int h = (v + 128) >> 8;
    hi = (int8_t)h;
    lo = (int8_t)(v - (h << 8));
}

// ===========================================================================
// Weight column max: sB[z][n] = max_k |W[z][k][n]|  -> quant/dequant mults
// block (32 n, 8 k-slices), grid (E/32, 4)
// ===========================================================================
__global__ void wcolmax_kernel(const float* __restrict__ qkv_w,
                               const float* __restrict__ o_w)
{
    __shared__ float red[8][32];
    int z = blockIdx.y;
    const float* W = (z < 3) ? qkv_w + (size_t)z * E_DIM * E_DIM : o_w;
    int n = blockIdx.x * 32 + threadIdx.x;
    float mx = 1e-30f;
    for (int k = threadIdx.y; k < E_DIM; k += 8)
        mx = fmaxf(mx, fabsf(W[(size_t)k * E_DIM + n]));
    red[threadIdx.y][threadIdx.x] = mx;
    __syncthreads();
    if (threadIdx.y == 0) {
        #pragma unroll
        for (int j = 1; j < 8; j++) mx = fmaxf(mx, red[j][threadIdx.x]);
        g_qb[z * E_DIM + n] = QMAX / mx;
        g_rb[z * E_DIM + n] = mx / QMAX;
    }
}

// ===========================================================================
// Weight transpose + int8 quant: W[z][k][n] -> W8[z][n][k] hi/lo
// ===========================================================================
__global__ void transpose_quant_kernel(const float* __restrict__ qkv_w,
                                       const float* __restrict__ o_w)
{
    __shared__ float tile[32][33];
    int z = blockIdx.z;
    const float* src = (z < 3) ? qkv_w + (size_t)z * E_DIM * E_DIM : o_w;
    int8_t* dhi = g_w8h + (size_t)z * E_DIM * E_DIM;
    int8_t* dlo = g_w8l + (size_t)z * E_DIM * E_DIM;
    int k0 = blockIdx.y * 32, n0 = blockIdx.x * 32;
    int tx = threadIdx.x, ty = threadIdx.y;
    #pragma unroll
    for (int j = 0; j < 32; j += 8)
        tile[ty + j][tx] = src[(size_t)(k0 + ty + j) * E_DIM + n0 + tx];
    __syncthreads();
    #pragma unroll
    for (int j = 0; j < 32; j += 8) {
        int n = n0 + ty + j;
        float q = g_qb[z * E_DIM + n];
        int8_t hi, lo;
        quant16(tile[tx][ty + j], q, hi, lo);
        size_t off = (size_t)n * E_DIM + k0 + tx;
        dhi[off] = hi;
        dlo[off] = lo;
    }
}

// ===========================================================================
// Activation row max: qa/ra per row. block 256, grid T_TOK.
// ===========================================================================
__global__ void rowmax_kernel(const float* __restrict__ x)
{
    __shared__ float red[8];
    int row = blockIdx.x;
    const float* xr = x + (size_t)row * E_DIM;
    float mx = 1e-30f;
    #pragma unroll 4
    for (int c = threadIdx.x; c < E_DIM; c += 256)
        mx = fmaxf(mx, fabsf(xr[c]));
    #pragma unroll
    for (int s = 16; s > 0; s >>= 1)
        mx = fmaxf(mx, __shfl_xor_sync(0xffffffffu, mx, s));
    if ((threadIdx.x & 31) == 0) red[threadIdx.x >> 5] = mx;
    __syncthreads();
    if (threadIdx.x == 0) {
        #pragma unroll
        for (int j = 1; j < 8; j++) mx = fmaxf(mx, red[j]);
        g_qa[row] = QMAX / mx;
        g_ra[row] = mx / QMAX;
    }
}

// ===========================================================================
// Activation quant: x[T,E] fp32 -> int8 hi/lo planes (4 elems/thread, same row)
// ===========================================================================
__global__ void quant_a_kernel(const float* __restrict__ x)
{
    long long i = ((long long)blockIdx.x * blockDim.x + threadIdx.x) * 4;
    if (i >= (long long)T_TOK * E_DIM) return;
    int row = (int)(i >> 12);
    float q = g_qa[row];
    float4 v = *(const float4*)&x[i];
    int8_t h0, h1, h2, h3, l0, l1, l2, l3;
    quant16(v.x, q, h0, l0);
    quant16(v.y, q, h1, l1);
    quant16(v.z, q, h2, l2);
    quant16(v.w, q, h3, l3);
    uchar4 hv = make_uchar4((uint8_t)h0, (uint8_t)h1, (uint8_t)h2, (uint8_t)h3);
    uchar4 lv = make_uchar4((uint8_t)l0, (uint8_t)l1, (uint8_t)l2, (uint8_t)l3);
    *(uchar4*)&g_a8h[i] = hv;
    *(uchar4*)&g_a8l[i] = lv;
}

// ===========================================================================
// int8 split GEMM: C[z][m][n] = sum_k A[m][k]*Bt[z][n][k], dequant in epilogue.
// Block tile 128x128, K-tile 32 (int8), 8 warps (2Mx4N), warp tile 64x32.
// Row layout: 128 rows x 80B (hi 32B | lo 32B | 16B pad) per matrix per stage.
// 2-stage cp.async double buffer, wait->barrier, occupancy 1 (acc pressure).
// ===========================================================================
#define KT 32
#define NK_ITERS (E_DIM / KT)              // 128
#define ROW_B 80
#define TILE_B (128 * ROW_B)               // 10240
#define STAGE_B (2 * TILE_B)               // 20480
#define GEMM_SMEM (2 * STAGE_B)            // 40960

__device__ __forceinline__ void stage_load(uint32_t smb, int st,
                                           const int8_t* __restrict__ Ahi,
                                           const int8_t* __restrict__ Alo,
                                           const int8_t* __restrict__ Bhi,
                                           const int8_t* __restrict__ Blo,
                                           int k0, int tid)
{
    #pragma unroll
    for (int j = 0; j < 4; ++j) {
        int idx = tid + 256 * j;
        int m   = idx >> 9;
        int r   = (idx >> 2) & 127;
        int seg = idx & 3;                 // 0,1 = hi 16B halves ; 2,3 = lo
        uint32_t dst = smb + st * STAGE_B + m * TILE_B + r * ROW_B + seg * 16;
        const int8_t* hp = m ? Bhi : Ahi;
        const int8_t* lp = m ? Blo : Alo;
        const int8_t* src = (seg < 2 ? hp : lp) + (long long)r * E_DIM + k0 + (seg & 1) * 16;
        cp16(dst, src);
    }
}

__global__ __launch_bounds__(256, 1)
void gemm_s8_kernel(const int8_t* __restrict__ Ahi, const int8_t* __restrict__ Alo,
                    const int8_t* __restrict__ Bhi, const int8_t* __restrict__ Blo,
                    const float* __restrict__ ra, const float* __restrict__ rb,
                    float* __restrict__ C,
                    long long strideB, long long strideRB, long long strideC)
{
    extern __shared__ char sm[];
    uint32_t smb = smem_u32(sm);
    const int tid = threadIdx.x;
    const int wid = tid >> 5;
    const int lane = tid & 31;
    const int grp = lane >> 2;
    const int thr = lane & 3;
    const int warp_m = wid >> 2;
    const int warp_n = wid & 3;

    const int m0 = blockIdx.y * 128;
    const int n0 = blockIdx.x * 128;
    const int8_t* Ah = Ahi + (long long)m0 * E_DIM;
    const int8_t* Al = Alo + (long long)m0 * E_DIM;
    const int8_t* Bh = Bhi + (long long)blockIdx.z * strideB + (long long)n0 * E_DIM;
    const int8_t* Bl = Blo + (long long)blockIdx.z * strideB + (long long)n0 * E_DIM;
    const float* rbp = rb + (long long)blockIdx.z * strideRB + n0;
    float* Cg = C + (long long)blockIdx.z * strideC;

    int acc_hh[4][4][4], acc_md[4][4][4];
    #pragma unroll
    for (int mi = 0; mi < 4; mi++)
        #pragma unroll
        for (int ni = 0; ni < 4; ni++)
            #pragma unroll
            for (int q = 0; q < 4; q++) { acc_hh[mi][ni][q] = 0; acc_md[mi][ni][q] = 0; }

    const uint32_t a_lane_off =
        (uint32_t)((warp_m * 64 + (lane & 15)) * ROW_B + (lane >> 4) * 16);
    const uint32_t b_lane_off =
        (uint32_t)((warp_n * 32 + (lane >> 4) * 8 + (lane & 7)) * ROW_B + ((lane >> 3) & 1) * 16);

    stage_load(smb, 0, Ah, Al, Bh, Bl, 0, tid);
    CP_COMMIT();

    for (int kt = 0; kt < NK_ITERS; ++kt) {
        int st = kt & 1;
        CP_WAIT0();
        __syncthreads();

        if (kt + 1 < NK_ITERS) {
            stage_load(smb, (kt + 1) & 1, Ah, Al, Bh, Bl, (kt + 1) * KT, tid);
            CP_COMMIT();
        }

        uint32_t abase = smb + st * STAGE_B + a_lane_off;
        uint32_t bbase = smb + st * STAGE_B + TILE_B + b_lane_off;

        uint32_t ah[4][4], al[4][4];
        #pragma unroll
        for (int mi = 0; mi < 4; mi++) {
            ldmatrix_x4(ah[mi], abase + mi * 16 * ROW_B);        // hi bytes 0..31
            ldmatrix_x4(al[mi], abase + mi * 16 * ROW_B + 32);   // lo bytes 32..63
        }
        #pragma unroll
        for (int g = 0; g < 2; g++) {
            uint32_t bh[4], bl[4];
            ldmatrix_x4(bh, bbase + g * 16 * ROW_B);
            ldmatrix_x4(bl, bbase + g * 16 * ROW_B + 32);
            #pragma unroll
            for (int mi = 0; mi < 4; mi++)
                #pragma unroll
                for (int nj = 0; nj < 2; nj++) {
                    int ni = g * 2 + nj;
                    mma_s8(acc_hh[mi][ni], ah[mi], &bh[nj * 2]);
                    mma_s8(acc_md[mi][ni], ah[mi], &bl[nj * 2]);
                    mma_s8(acc_md[mi][ni], al[mi], &bh[nj * 2]);
                }
        }
    }

    // epilogue: dequant + store
    #pragma unroll
    for (int mi = 0; mi < 4; mi++) {
        long long r0 = m0 + warp_m * 64 + mi * 16 + grp;
        float ra0 = ra[r0];
        float ra1 = ra[r0 + 8];
        #pragma unroll
        for (int ni = 0; ni < 4; ni++) {
            int coln = warp_n * 32 + ni * 8 + thr * 2;
            float rb0 = rbp[coln];
            float rb1 = rbp[coln + 1];
            long long col = n0 + coln;
            float v00 = ((float)acc_hh[mi][ni][0] * 65536.f + (float)acc_md[mi][ni][0] * 256.f) * ra0 * rb0;
            float v01 = ((float)acc_hh[mi][ni][1] * 65536.f + (float)acc_md[mi][ni][1] * 256.f) * ra0 * rb1;
            float v10 = ((float)acc_hh[mi][ni][2] * 65536.f + (float)acc_md[mi][ni][2] * 256.f) * ra1 * rb0;
            float v11 = ((float)acc_hh[mi][ni][3] * 65536.f + (float)acc_md[mi][ni][3] * 256.f) * ra1 * rb1;
            *(float2*)&Cg[r0 * E_DIM + col]       = make_float2(v00, v01);
            *(float2*)&Cg[(r0 + 8) * E_DIM + col] = make_float2(v10, v11);
        }
    }
}

// ===========================================================================
// RoPE (in-place on q and k slices of g_qkv)
// ===========================================================================
__global__ void rope_kernel(float* __restrict__ qkv,
                            const float* __restrict__ cosv,
                            const float* __restrict__ sinv)
{
    long long idx = (long long)blockIdx.x * blockDim.x + threadIdx.x;
    if (idx >= 2LL * T_TOK * H_NUM * 64) return;
    int j = idx & 63;
    int h = (idx >> 6) & (H_NUM - 1);
    long long t = (idx >> 11) & (T_TOK - 1);
    int which = (int)(idx >> 23);
    float* base = qkv + (long long)which * T_TOK * E_DIM + t * E_DIM + h * D_HEAD;
    float c = cosv[t * 64 + j];
    float s = sinv[t * 64 + j];
    float x1 = base[j];
    float x2 = base[j + 64];
    base[j]      = x1 * c - x2 * s;
    base[j + 64] = x2 * c + x1 * s;
}

// ===========================================================================
// KV cache scatter
// ===========================================================================
__global__ void cache_write_kernel(const float* __restrict__ qkv,
                                   const int* __restrict__ block_tables,
                                   float* __restrict__ out_k,
                                   float* __restrict__ out_v)
{
    long long idx = (long long)blockIdx.x * blockDim.x + threadIdx.x;
    if (idx >= (long long)B_SZ * NB_BLK * H_NUM * BS_BLK * D_HEAD) return;
    int d  = idx & 127;
    int bs = (idx >> 7) & (BS_BLK - 1);
    int h  = (idx >> 11) & (H_NUM - 1);
    long long nbb = idx >> 16;
    int b  = (int)(nbb >> 6);
    int nb = (int)(nbb & 63);
    int blk = block_tables[b * NB_BLK + nb];
    long long t = (long long)b * S_LEN + nb * BS_BLK + bs;
    long long src = t * E_DIM + h * D_HEAD + d;
    long long dst = (((long long)blk * H_NUM + h) * BS_BLK + bs) * D_HEAD + d;
    out_k[dst] = qkv[(long long)T_TOK * E_DIM + src];
    out_v[dst] = qkv[2LL * T_TOK * E_DIM + src];
}

// ===========================================================================
// Flash attention, fp32 with packed f32x2 FMA, causal. fp32 output.
// ===========================================================================
#define QS_STRIDE 130
#define KS_STRIDE 130
#define VS_STRIDE 132
#define PS_STRIDE 65

__global__ __launch_bounds__(256, 1)
void attn_kernel(const float* __restrict__ qkv, float* __restrict__ attn_out)
{
    extern __shared__ float smf[];
    float* Qs = smf;
    float* Ks = Qs + 64 * QS_STRIDE;
    float* Vs = Ks + 64 * KS_STRIDE;
    float* Ps = Vs + 64 * VS_STRIDE;
    float* alpha_sh = Ps + 64 * PS_STRIDE;
    float* l_sh = alpha_sh + 64;

    int tid = threadIdx.x;
    int tx = tid & 15, ty = tid >> 4;
    int qt = blockIdx.x, h = blockIdx.y, b = blockIdx.z;
    int q0 = qt * 64;

    const long long TE = (long long)T_TOK * E_DIM;
    const float* qbase = qkv;
    const float* kbase = qkv + TE;
    const float* vbase = qkv + 2 * TE;
    const float scale = 0.08838834764831845f;

    for (int c = tid; c < 64 * 32; c += 256) {
        int row = c >> 5;
        int c4 = (c & 31) * 4;
        float4 v = *(const float4*)&qbase[((long long)(b * S_LEN + q0 + row)) * E_DIM + h * D_HEAD + c4];
        *(float2*)&Qs[row * QS_STRIDE + c4]     = make_float2(v.x, v.y);
        *(float2*)&Qs[row * QS_STRIDE + c4 + 2] = make_float2(v.z, v.w);
    }

    float m_r = -1e30f, l_r = 0.f;
    uint64_t o2[4][4];
    #pragma unroll
    for (int i = 0; i < 4; i++)
        #pragma unroll
        for (int j = 0; j < 4; j++) o2[i][j] = 0ull;

    int nkt = qt + 1;
    for (int kt = 0; kt < nkt; kt++) {
        int k0 = kt * 64;
        __syncthreads();
        for (int c = tid; c < 64 * 32; c += 256) {
            int row = c >> 5;
            int c4 = (c & 31) * 4;
            long long goff = ((long long)(b * S_LEN + k0 + row)) * E_DIM + h * D_HEAD + c4;
            float4 kv = *(const float4*)&kbase[goff];
            *(float2*)&Ks[row * KS_STRIDE + c4]     = make_float2(kv.x, kv.y);
            *(float2*)&Ks[row * KS_STRIDE + c4 + 2] = make_float2(kv.z, kv.w);
            float4 vv = *(const float4*)&vbase[goff];
            *(float4*)&Vs[row * VS_STRIDE + c4] = vv;
        }
        __syncthreads();

        uint64_t s2[4][4];
        #pragma unroll
        for (int i = 0; i < 4; i++)
            #pragma unroll
            for (int j = 0; j < 4; j++) s2[i][j] = 0ull;
        const float* qr0 = &Qs[(ty +  0) * QS_STRIDE];
        const float* qr1 = &Qs[(ty + 16) * QS_STRIDE];
        const float* qr2 = &Qs[(ty + 32) * QS_STRIDE];
        const float* qr3 = &Qs[(ty + 48) * QS_STRIDE];
        const float* kr0 = &Ks[(tx +  0) * KS_STRIDE];
        const float* kr1 = &Ks[(tx + 16) * KS_STRIDE];
        const float* kr2 = &Ks[(tx + 32) * KS_STRIDE];
        const float* kr3 = &Ks[(tx + 48) * KS_STRIDE];
        #pragma unroll 4
        for (int d = 0; d < 128; d += 2) {
            uint64_t a0 = *(const uint64_t*)(qr0 + d);
            uint64_t a1 = *(const uint64_t*)(qr1 + d);
            uint64_t a2 = *(const uint64_t*)(qr2 + d);
            uint64_t a3 = *(const uint64_t*)(qr3 + d);
            uint64_t b0 = *(const uint64_t*)(kr0 + d);
            uint64_t b1 = *(const uint64_t*)(kr1 + d);
            uint64_t b2 = *(const uint64_t*)(kr2 + d);
            uint64_t b3 = *(const uint64_t*)(kr3 + d);
            FMA2(s2[0][0], a0, b0); FMA2(s2[0][1], a0, b1); FMA2(s2[0][2], a0, b2); FMA2(s2[0][3], a0, b3);
            FMA2(s2[1][0], a1, b0); FMA2(s2[1][1], a1, b1); FMA2(s2[1][2], a1, b2); FMA2(s2[1][3], a1, b3);
            FMA2(s2[2][0], a2, b0); FMA2(s2[2][1], a2, b1); FMA2(s2[2][2], a2, b2); FMA2(s2[2][3], a2, b3);
            FMA2(s2[3][0], a3, b0); FMA2(s2[3][1], a3, b1); FMA2(s2[3][2], a3, b2); FMA2(s2[3][3], a3, b3);
        }
        bool diag = (kt == qt);
        #pragma unroll
        for (int i = 0; i < 4; i++) {
            int qi = ty + 16 * i;
            #pragma unroll
            for (int j = 0; j < 4; j++) {
                int ki = tx + 16 * j;
                float lo, hi;
                UNPACK2(lo, hi, s2[i][j]);
                float val = (lo + hi) * scale;
                if (diag && ki > qi) val = -1e30f;
                Ps[qi * PS_STRIDE + ki] = val;
            }
        }
        __syncthreads();

        {
            int q = tid >> 2;
            int cc = (tid & 3) * 16;
            float* pr = &Ps[q * PS_STRIDE + cc];
            float mx = -1e30f;
            #pragma unroll
            for (int c = 0; c < 16; c++) mx = fmaxf(mx, pr[c]);
            mx = fmaxf(mx, __shfl_xor_sync(0xffffffffu, mx, 1));
            mx = fmaxf(mx, __shfl_xor_sync(0xffffffffu, mx, 2));
            float m_new = fmaxf(m_r, mx);
            float al = __expf(m_r - m_new);
            float sum = 0.f;
            #pragma unroll
            for (int c = 0; c < 16; c++) {
                float p = __expf(pr[c] - m_new);
                pr[c] = p;
                sum += p;
            }
            sum += __shfl_xor_sync(0xffffffffu, sum, 1);
            sum += __shfl_xor_sync(0xffffffffu, sum, 2);
            l_r = l_r * al + sum;
            m_r = m_new;
            if ((tid & 3) == 0) { alpha_sh[q] = al; l_sh[q] = l_r; }
        }
        __syncthreads();

        #pragma unroll
        for (int i = 0; i < 4; i++) {
            float av = alpha_sh[ty + 16 * i];
            uint64_t avp; PACK2(avp, av, av);
            #pragma unroll
            for (int j = 0; j < 4; j++) { uint64_t t; MUL2(t, o2[i][j], avp); o2[i][j] = t; }
        }

        #pragma unroll 2
        for (int k = 0; k < 64; k++) {
            float p0 = Ps[(ty +  0) * PS_STRIDE + k];
            float p1 = Ps[(ty + 16) * PS_STRIDE + k];
            float p2 = Ps[(ty + 32) * PS_STRIDE + k];
            float p3 = Ps[(ty + 48) * PS_STRIDE + k];
            uint64_t pp0, pp1, pp2, pp3;
            PACK2(pp0, p0, p0); PACK2(pp1, p1, p1);
            PACK2(pp2, p2, p2); PACK2(pp3, p3, p3);
            float4 v0 = *(float4*)&Vs[k * VS_STRIDE + tx * 8];
            float4 v1 = *(float4*)&Vs[k * VS_STRIDE + tx * 8 + 4];
            uint64_t vv0, vv1, vv2, vv3;
            PACK2(vv0, v0.x, v0.y); PACK2(vv1, v0.z, v0.w);
            PACK2(vv2, v1.x, v1.y); PACK2(vv3, v1.z, v1.w);
            FMA2(o2[0][0], pp0, vv0); FMA2(o2[0][1], pp0, vv1); FMA2(o2[0][2], pp0, vv2); FMA2(o2[0][3], pp0, vv3);
            FMA2(o2[1][0], pp1, vv0); FMA2(o2[1][1], pp1, vv1); FMA2(o2[1][2], pp1, vv2); FMA2(o2[1][3], pp1, vv3);
            FMA2(o2[2][0], pp2, vv0); FMA2(o2[2][1], pp2, vv1); FMA2(o2[2][2], pp2, vv2); FMA2(o2[2][3], pp2, vv3);
            FMA2(o2[3][0], pp3, vv0); FMA2(o2[3][1], pp3, vv1); FMA2(o2[3][2], pp3, vv2); FMA2(o2[3][3], pp3, vv3);
        }
    }

    #pragma unroll
    for (int i = 0; i < 4; i++) {
        int qi = ty + 16 * i;
        float inv = 1.f / l_sh[qi];
        long long off = ((long long)(b * S_LEN + q0 + qi)) * E_DIM + h * D_HEAD + tx * 8;
        float e0, e1, e2, e3, e4, e5, e6, e7;
        UNPACK2(e0, e1, o2[i][0]);
        UNPACK2(e2, e3, o2[i][1]);
        UNPACK2(e4, e5, o2[i][2]);
        UNPACK2(e6, e7, o2[i][3]);
        *(float4*)&attn_out[off]     = make_float4(e0 * inv, e1 * inv, e2 * inv, e3 * inv);
        *(float4*)&attn_out[off + 4] = make_float4(e4 * inv, e5 * inv, e6 * inv, e7 * inv);
    }
}

// ===========================================================================
extern "C" void kernel_launch(void* const* d_in, const int* in_sizes, int n_in,
                              void* d_out, int out_size)
{
    const float* hidden   = (const float*)d_in[0];
    const float* qkv_w    = (const float*)d_in[1];
    const float* o_w      = (const float*)d_in[2];
    const float* cosv     = (const float*)d_in[3];
    const float* sinv     = (const float*)d_in[4];
    const int*   blk_tab  = (const int*)d_in[7];

    float* out   = (float*)d_out;
    float* out_k = out + (size_t)T_TOK * E_DIM;
    float* out_v = out_k + (size_t)T_TOK * E_DIM;

    float*  qkv;  cudaGetSymbolAddress((void**)&qkv,  g_qkv);
    float*  attn; cudaGetSymbolAddress((void**)&attn, g_attn);
    int8_t* w8h;  cudaGetSymbolAddress((void**)&w8h,  g_w8h);
    int8_t* w8l;  cudaGetSymbolAddress((void**)&w8l,  g_w8l);
    int8_t* a8h;  cudaGetSymbolAddress((void**)&a8h,  g_a8h);
    int8_t* a8l;  cudaGetSymbolAddress((void**)&a8l,  g_a8l);
    float*  rap;  cudaGetSymbolAddress((void**)&rap,  g_ra);
    float*  rbp;  cudaGetSymbolAddress((void**)&rbp,  g_rb);

    // 0) Weight scales + transpose/quant; activation scales + quant
    wcolmax_kernel<<<dim3(E_DIM / 32, 4), dim3(32, 8)>>>(qkv_w, o_w);
    transpose_quant_kernel<<<dim3(E_DIM / 32, E_DIM / 32, 4), dim3(32, 8)>>>(qkv_w, o_w);
    rowmax_kernel<<<T_TOK, 256>>>(hidden);
    {
        long long total = (long long)T_TOK * E_DIM / 4;
        quant_a_kernel<<<(unsigned)((total + 255) / 256), 256>>>(hidden);
    }

    // 1) QKV projection (int8 split mma)
    cudaFuncSetAttribute(gemm_s8_kernel, cudaFuncAttributeMaxDynamicSharedMemorySize, GEMM_SMEM);
    gemm_s8_kernel<<<dim3(E_DIM / 128, T_TOK / 128, 3), 256, GEMM_SMEM>>>(
        a8h, a8l, w8h, w8l, rap, rbp, qkv,
        (long long)E_DIM * E_DIM, (long long)E_DIM, (long long)T_TOK * E_DIM);

    // 2) RoPE
    {
        long long total = 2LL * T_TOK * H_NUM * 64;
        rope_kernel<<<(unsigned)((total + 255) / 256), 256>>>(qkv, cosv, sinv);
    }

    // 3) KV cache scatter
    {
        long long total = (long long)B_SZ * NB_BLK * H_NUM * BS_BLK * D_HEAD;
        cache_write_kernel<<<(unsigned)((total + 255) / 256), 256>>>(qkv, blk_tab, out_k, out_v);
    }

    // 4) Flash attention (packed f32x2, fp32 out)
    {
        int smem = (64 * QS_STRIDE + 64 * KS_STRIDE + 64 * VS_STRIDE +
                    64 * PS_STRIDE + 64 + 64) * (int)sizeof(float);
        cudaFuncSetAttribute(attn_kernel, cudaFuncAttributeMaxDynamicSharedMemorySize, smem);
        attn_kernel<<<dim3(S_LEN / 64, H_NUM, B_SZ), 256, smem>>>(qkv, attn);
    }

    // 5) Quantize attention output, then O-projection (int8 split mma)
    rowmax_kernel<<<T_TOK, 256>>>(attn);
    {
        long long total = (long long)T_TOK * E_DIM / 4;
        quant_a_kernel<<<(unsigned)((total + 255) / 256), 256>>>(attn);
    }
    gemm_s8_kernel<<<dim3(E_DIM / 128, T_TOK / 128, 1), 256, GEMM_SMEM>>>(
        a8h, a8l, w8h + 3ULL * E_DIM * E_DIM, w8l + 3ULL * E_DIM * E_DIM,
        rap, rbp + 3ULL * E_DIM, out, 0, 0, 0);
}

// round 15
// speedup vs baseline: 1.2918x; 1.2918x over previous
#include <cuda_runtime.h>
#include <cuda_fp16.h>
#include <cstdint>

#define T_TOK 4096
#define E_DIM 4096
#define B_SZ  4
#define S_LEN 1024
#define H_NUM 32
#define D_HEAD 128
#define BS_BLK 16
#define NB_BLK 64

// Scratch (allocation-free rule: __device__ globals)
__device__ float  g_qkv[3ULL * T_TOK * E_DIM];        // q | k | v fp32
__device__ __half g_wt_hi[4ULL * E_DIM * E_DIM];      // transposed weight hi planes [4][N][K]
__device__ __half g_wt_lo[4ULL * E_DIM * E_DIM];      // transposed weight lo planes
__device__ __half g_ahi[(size_t)T_TOK * E_DIM];       // activation hi plane [T, E]
__device__ __half g_alo[(size_t)T_TOK * E_DIM];       // activation lo plane

// ===========================================================================
// helpers
// ===========================================================================
__device__ __forceinline__ uint32_t smem_u32(const void* p) {
    uint32_t a;
    asm("{ .reg .u64 t; cvta.to.shared.u64 t, %1; cvt.u32.u64 %0, t; }" : "=r"(a) : "l"(p));
    return a;
}
__device__ __forceinline__ void cp16(uint32_t dst, const void* src) {
    asm volatile("cp.async.ca.shared.global [%0], [%1], 16;" :: "r"(dst), "l"(src));
}
#define CP_COMMIT() asm volatile("cp.async.commit_group;" ::: "memory")
#define CP_WAIT0()  asm volatile("cp.async.wait_group 0;" ::: "memory")

__device__ __forceinline__ void mma_f16(float* c, const uint32_t* a, const uint32_t* b) {
    asm volatile(
        "mma.sync.aligned.m16n8k16.row.col.f32.f16.f16.f32 "
        "{%0,%1,%2,%3}, {%4,%5,%6,%7}, {%8,%9}, {%0,%1,%2,%3};"
        : "+f"(c[0]), "+f"(c[1]), "+f"(c[2]), "+f"(c[3])
        : "r"(a[0]), "r"(a[1]), "r"(a[2]), "r"(a[3]), "r"(b[0]), "r"(b[1]));
}
// f16-accumulate variant (cross terms): d,c packed as 2x half2
__device__ __forceinline__ void mma_f16acc(uint32_t* c, const uint32_t* a, const uint32_t* b) {
    asm volatile(
        "mma.sync.aligned.m16n8k16.row.col.f16.f16.f16.f16 "
        "{%0,%1}, {%2,%3,%4,%5}, {%6,%7}, {%0,%1};"
        : "+r"(c[0]), "+r"(c[1])
        : "r"(a[0]), "r"(a[1]), "r"(a[2]), "r"(a[3]), "r"(b[0]), "r"(b[1]));
}
__device__ __forceinline__ void ldmatrix_x4(uint32_t* r, uint32_t addr) {
    asm volatile("ldmatrix.sync.aligned.m8n8.x4.shared.b16 {%0,%1,%2,%3}, [%4];"
                 : "=r"(r[0]), "=r"(r[1]), "=r"(r[2]), "=r"(r[3]) : "r"(addr));
}

// Packed fp32x2 ops (Blackwell)
#define FMA2(acc, a, b) \
    asm("fma.rn.f32x2 %0, %1, %2, %0;" : "+l"(acc) : "l"(a), "l"(b))
#define MUL2(out, a, b) \
    asm("mul.rn.f32x2 %0, %1, %2;" : "=l"(out) : "l"(a), "l"(b))
#define PACK2(out, lo, hi) \
    asm("mov.b64 %0, {%1, %2};" : "=l"(out) : "f"(lo), "f"(hi))
#define UNPACK2(lo, hi, in) \
    asm("mov.b64 {%0, %1}, %2;" : "=f"(lo), "=f"(hi) : "l"(in))

// ===========================================================================
// Weight transpose + hi/lo split: W[z][k][n] fp32 -> Wt_hi/lo[z][n][k] half
// ===========================================================================
__global__ void transpose_split_kernel(const float* __restrict__ qkv_w,
                                       const float* __restrict__ o_w,
                                       __half* __restrict__ out_hi,
                                       __half* __restrict__ out_lo)
{
    __shared__ float tile[32][33];
    int z = blockIdx.z;
    const float* src = (z < 3) ? qkv_w + (size_t)z * E_DIM * E_DIM : o_w;
    __half* dhi = out_hi + (size_t)z * E_DIM * E_DIM;
    __half* dlo = out_lo + (size_t)z * E_DIM * E_DIM;
    int k0 = blockIdx.y * 32, n0 = blockIdx.x * 32;
    int tx = threadIdx.x, ty = threadIdx.y;
    #pragma unroll
    for (int j = 0; j < 32; j += 8)
        tile[ty + j][tx] = src[(size_t)(k0 + ty + j) * E_DIM + n0 + tx];
    __syncthreads();
    #pragma unroll
    for (int j = 0; j < 32; j += 8) {
        float x = tile[tx][ty + j];
        __half hi = __float2half_rn(x);
        __half lo = __float2half_rn(x - __half2float(hi));
        size_t off = (size_t)(n0 + ty + j) * E_DIM + k0 + tx;
        dhi[off] = hi;
        dlo[off] = lo;
    }
}

// ===========================================================================
// Activation hi/lo split: X[T,E] fp32 -> hi/lo half planes
// ===========================================================================
__global__ void split_a_kernel(const float* __restrict__ x,
                               __half* __restrict__ xhi, __half* __restrict__ xlo)
{
    long long i = ((long long)blockIdx.x * blockDim.x + threadIdx.x) * 4;
    if (i >= (long long)T_TOK * E_DIM) return;
    float4 v = *(const float4*)&x[i];
    __half h0 = __float2half_rn(v.x), h1 = __float2half_rn(v.y);
    __half h2 = __float2half_rn(v.z), h3 = __float2half_rn(v.w);
    __half l0 = __float2half_rn(v.x - __half2float(h0));
    __half l1 = __float2half_rn(v.y - __half2float(h1));
    __half l2 = __float2half_rn(v.z - __half2float(h2));
    __half l3 = __float2half_rn(v.w - __half2float(h3));
    *(half2*)&xhi[i]     = __halves2half2(h0, h1);
    *(half2*)&xhi[i + 2] = __halves2half2(h2, h3);
    *(half2*)&xlo[i]     = __halves2half2(l0, l1);
    *(half2*)&xlo[i + 2] = __halves2half2(l2, l3);
}

// ===========================================================================
// fp16 hi/lo split GEMM, f16-accum cross terms. C[z] = A @ Bt[z] (fp32 out)
// Block tile 128x128, K-tile 16, 16 warps (4Mx4N), warp tile 32x32.
// Row layout per stage: 128 rows x 80B (hi 32B | lo 32B | 16B pad) per matrix.
// 2-stage cp.async double buffer, wait->barrier order, 2 CTAs/SM.
// ===========================================================================
#define KT 16
#define NK_ITERS (E_DIM / KT)              // 256
#define ROW_B 80
#define TILE_B (128 * ROW_B)               // 10240
#define STAGE_B (2 * TILE_B)               // 20480
#define GEMM_SMEM (2 * STAGE_B)            // 40960

__device__ __forceinline__ void stage_load(uint32_t smb, int st,
                                           const __half* __restrict__ Ahi,
                                           const __half* __restrict__ Alo,
                                           const __half* __restrict__ Bhi,
                                           const __half* __restrict__ Blo,
                                           int k0, int tid)
{
    #pragma unroll
    for (int j = 0; j < 2; ++j) {
        int idx = tid + 512 * j;
        int m   = idx >> 9;
        int r   = (idx >> 2) & 127;
        int seg = idx & 3;                 // 0,1 = hi halves ; 2,3 = lo halves
        uint32_t dst = smb + st * STAGE_B + m * TILE_B + r * ROW_B + seg * 16;
        const __half* hp = m ? Bhi : Ahi;
        const __half* lp = m ? Blo : Alo;
        const __half* src = (seg < 2 ? hp : lp) + (long long)r * E_DIM + k0 + (seg & 1) * 8;
        cp16(dst, src);
    }
}

__global__ __launch_bounds__(512, 2)
void gemm_mma_kernel(const __half* __restrict__ Ahi, const __half* __restrict__ Alo,
                     const __half* __restrict__ Bhi, const __half* __restrict__ Blo,
                     float* __restrict__ C, long long strideB, long long strideC)
{
    extern __shared__ char sm[];
    uint32_t smb = smem_u32(sm);
    const int tid = threadIdx.x;
    const int wid = tid >> 5;        // 0..15
    const int lane = tid & 31;
    const int grp = lane >> 2;
    const int thr = lane & 3;
    const int warp_m = wid >> 2;     // 0..3
    const int warp_n = wid & 3;      // 0..3

    const int m0 = blockIdx.y * 128;
    const int n0 = blockIdx.x * 128;
    const __half* Ah = Ahi + (long long)m0 * E_DIM;
    const __half* Al = Alo + (long long)m0 * E_DIM;
    const __half* Bh = Bhi + (long long)blockIdx.z * strideB + (long long)n0 * E_DIM;
    const __half* Bl = Blo + (long long)blockIdx.z * strideB + (long long)n0 * E_DIM;
    float* Cg = C + (long long)blockIdx.z * strideC;

    float acc[2][4][4];          // main (hi*hi), f32 accum
    uint32_t accx[2][4][2];      // cross terms, f16 accum (2x half2)
    #pragma unroll
    for (int mi = 0; mi < 2; mi++)
        #pragma unroll
        for (int ni = 0; ni < 4; ni++) {
            #pragma unroll
            for (int q = 0; q < 4; q++) acc[mi][ni][q] = 0.f;
            accx[mi][ni][0] = 0u; accx[mi][ni][1] = 0u;
        }

    const uint32_t a_lane_off =
        (uint32_t)((warp_m * 32 + (lane & 15)) * ROW_B + (lane >> 4) * 16);
    const uint32_t b_lane_off =
        (uint32_t)((warp_n * 32 + (lane >> 4) * 8 + (lane & 7)) * ROW_B + ((lane >> 3) & 1) * 16);

    stage_load(smb, 0, Ah, Al, Bh, Bl, 0, tid);
    CP_COMMIT();

    for (int kt = 0; kt < NK_ITERS; ++kt) {
        int st = kt & 1;
        CP_WAIT0();        // load(kt) complete (this thread's copies)
        __syncthreads();   // ...visible block-wide; prev reads of buf^1 retired

        if (kt + 1 < NK_ITERS) {
            stage_load(smb, (kt + 1) & 1, Ah, Al, Bh, Bl, (kt + 1) * KT, tid);
            CP_COMMIT();
        }

        uint32_t abase = smb + st * STAGE_B + a_lane_off;
        uint32_t bbase = smb + st * STAGE_B + TILE_B + b_lane_off;

        uint32_t ah[2][4], al[2][4];
        #pragma unroll
        for (int mi = 0; mi < 2; mi++) {
            ldmatrix_x4(ah[mi], abase + mi * 16 * ROW_B);
            ldmatrix_x4(al[mi], abase + mi * 16 * ROW_B + 32);
        }
        #pragma unroll
        for (int g = 0; g < 2; g++) {
            uint32_t bh[4], bl[4];
            ldmatrix_x4(bh, bbase + g * 16 * ROW_B);
            ldmatrix_x4(bl, bbase + g * 16 * ROW_B + 32);
            #pragma unroll
            for (int mi = 0; mi < 2; mi++)
                #pragma unroll
                for (int nj = 0; nj < 2; nj++) {
                    int ni = g * 2 + nj;
                    mma_f16acc(accx[mi][ni], al[mi], &bh[nj * 2]);
                    mma_f16acc(accx[mi][ni], ah[mi], &bl[nj * 2]);
                    mma_f16(acc[mi][ni], ah[mi], &bh[nj * 2]);
                }
        }
    }

    // epilogue: main + cross, direct global stores
    #pragma unroll
    for (int mi = 0; mi < 2; mi++) {
        long long r0 = m0 + warp_m * 32 + mi * 16 + grp;
        #pragma unroll
        for (int ni = 0; ni < 4; ni++) {
            long long col = n0 + warp_n * 32 + ni * 8 + thr * 2;
            float2 x0 = __half22float2(*(half2*)&accx[mi][ni][0]);
            float2 x1 = __half22float2(*(half2*)&accx[mi][ni][1]);
            *(float2*)&Cg[r0 * E_DIM + col] =
                make_float2(acc[mi][ni][0] + x0.x, acc[mi][ni][1] + x0.y);
            *(float2*)&Cg[(r0 + 8) * E_DIM + col] =
                make_float2(acc[mi][ni][2] + x1.x, acc[mi][ni][3] + x1.y);
        }
    }
}

// ===========================================================================
// RoPE (in-place on q and k slices of g_qkv)
// ===========================================================================
__global__ void rope_kernel(float* __restrict__ qkv,
                            const float* __restrict__ cosv,
                            const float* __restrict__ sinv)
{
    long long idx = (long long)blockIdx.x * blockDim.x + threadIdx.x;
    if (idx >= 2LL * T_TOK * H_NUM * 64) return;
    int j = idx & 63;
    int h = (idx >> 6) & (H_NUM - 1);
    long long t = (idx >> 11) & (T_TOK - 1);
    int which = (int)(idx >> 23);   // 0 = q, 1 = k
    float* base = qkv + (long long)which * T_TOK * E_DIM + t * E_DIM + h * D_HEAD;
    float c = cosv[t * 64 + j];
    float s = sinv[t * 64 + j];
    float x1 = base[j];
    float x2 = base[j + 64];
    base[j]      = x1 * c - x2 * s;
    base[j + 64] = x2 * c + x1 * s;
}

// ===========================================================================
// KV cache scatter
// ===========================================================================
__global__ void cache_write_kernel(const float* __restrict__ qkv,
                                   const int* __restrict__ block_tables,
                                   float* __restrict__ out_k,
                                   float* __restrict__ out_v)
{
    long long idx = (long long)blockIdx.x * blockDim.x + threadIdx.x;
    if (idx >= (long long)B_SZ * NB_BLK * H_NUM * BS_BLK * D_HEAD) return;
    int d  = idx & 127;
    int bs = (idx >> 7) & (BS_BLK - 1);
    int h  = (idx >> 11) & (H_NUM - 1);
    long long nbb = idx >> 16;
    int b  = (int)(nbb >> 6);
    int nb = (int)(nbb & 63);
    int blk = block_tables[b * NB_BLK + nb];
    long long t = (long long)b * S_LEN + nb * BS_BLK + bs;
    long long src = t * E_DIM + h * D_HEAD + d;
    long long dst = (((long long)blk * H_NUM + h) * BS_BLK + bs) * D_HEAD + d;
    out_k[dst] = qkv[(long long)T_TOK * E_DIM + src];
    out_v[dst] = qkv[2LL * T_TOK * E_DIM + src];
}

// ===========================================================================
// Flash attention, fp32 with packed f32x2 FMA, causal.
// Writes hi/lo half planes for the O-proj GEMM.
// ===========================================================================
#define QS_STRIDE 130
#define KS_STRIDE 130
#define VS_STRIDE 132
#define PS_STRIDE 65

__global__ __launch_bounds__(256, 1)
void attn_kernel(const float* __restrict__ qkv,
                 __half* __restrict__ ohi, __half* __restrict__ olo)
{
    extern __shared__ float smf[];
    float* Qs = smf;
    float* Ks = Qs + 64 * QS_STRIDE;
    float* Vs = Ks + 64 * KS_STRIDE;
    float* Ps = Vs + 64 * VS_STRIDE;
    float* alpha_sh = Ps + 64 * PS_STRIDE;
    float* l_sh = alpha_sh + 64;

    int tid = threadIdx.x;
    int tx = tid & 15, ty = tid >> 4;
    int qt = blockIdx.x, h = blockIdx.y, b = blockIdx.z;
    int q0 = qt * 64;

    const long long TE = (long long)T_TOK * E_DIM;
    const float* qbase = qkv;
    const float* kbase = qkv + TE;
    const float* vbase = qkv + 2 * TE;
    const float scale = 0.08838834764831845f;

    for (int c = tid; c < 64 * 32; c += 256) {
        int row = c >> 5;
        int c4 = (c & 31) * 4;
        float4 v = *(const float4*)&qbase[((long long)(b * S_LEN + q0 + row)) * E_DIM + h * D_HEAD + c4];
        *(float2*)&Qs[row * QS_STRIDE + c4]     = make_float2(v.x, v.y);
        *(float2*)&Qs[row * QS_STRIDE + c4 + 2] = make_float2(v.z, v.w);
    }

    float m_r = -1e30f, l_r = 0.f;
    uint64_t o2[4][4];
    #pragma unroll
    for (int i = 0; i < 4; i++)
        #pragma unroll
        for (int j = 0; j < 4; j++) o2[i][j] = 0ull;

    int nkt = qt + 1;
    for (int kt = 0; kt < nkt; kt++) {
        int k0 = kt * 64;
        __syncthreads();
        for (int c = tid; c < 64 * 32; c += 256) {
            int row = c >> 5;
            int c4 = (c & 31) * 4;
            long long goff = ((long long)(b * S_LEN + k0 + row)) * E_DIM + h * D_HEAD + c4;
            float4 kv = *(const float4*)&kbase[goff];
            *(float2*)&Ks[row * KS_STRIDE + c4]     = make_float2(kv.x, kv.y);
            *(float2*)&Ks[row * KS_STRIDE + c4 + 2] = make_float2(kv.z, kv.w);
            float4 vv = *(const float4*)&vbase[goff];
            *(float4*)&Vs[row * VS_STRIDE + c4] = vv;
        }
        __syncthreads();

        uint64_t s2[4][4];
        #pragma unroll
        for (int i = 0; i < 4; i++)
            #pragma unroll
            for (int j = 0; j < 4; j++) s2[i][j] = 0ull;
        const float* qr0 = &Qs[(ty +  0) * QS_STRIDE];
        const float* qr1 = &Qs[(ty + 16) * QS_STRIDE];
        const float* qr2 = &Qs[(ty + 32) * QS_STRIDE];
        const float* qr3 = &Qs[(ty + 48) * QS_STRIDE];
        const float* kr0 = &Ks[(tx +  0) * KS_STRIDE];
        const float* kr1 = &Ks[(tx + 16) * KS_STRIDE];
        const float* kr2 = &Ks[(tx + 32) * KS_STRIDE];
        const float* kr3 = &Ks[(tx + 48) * KS_STRIDE];
        #pragma unroll 4
        for (int d = 0; d < 128; d += 2) {
            uint64_t a0 = *(const uint64_t*)(qr0 + d);
            uint64_t a1 = *(const uint64_t*)(qr1 + d);
            uint64_t a2 = *(const uint64_t*)(qr2 + d);
            uint64_t a3 = *(const uint64_t*)(qr3 + d);
            uint64_t b0 = *(const uint64_t*)(kr0 + d);
            uint64_t b1 = *(const uint64_t*)(kr1 + d);
            uint64_t b2 = *(const uint64_t*)(kr2 + d);
            uint64_t b3 = *(const uint64_t*)(kr3 + d);
            FMA2(s2[0][0], a0, b0); FMA2(s2[0][1], a0, b1); FMA2(s2[0][2], a0, b2); FMA2(s2[0][3], a0, b3);
            FMA2(s2[1][0], a1, b0); FMA2(s2[1][1], a1, b1); FMA2(s2[1][2], a1, b2); FMA2(s2[1][3], a1, b3);
            FMA2(s2[2][0], a2, b0); FMA2(s2[2][1], a2, b1); FMA2(s2[2][2], a2, b2); FMA2(s2[2][3], a2, b3);
            FMA2(s2[3][0], a3, b0); FMA2(s2[3][1], a3, b1); FMA2(s2[3][2], a3, b2); FMA2(s2[3][3], a3, b3);
        }
        bool diag = (kt == qt);
        #pragma unroll
        for (int i = 0; i < 4; i++) {
            int qi = ty + 16 * i;
            #pragma unroll
            for (int j = 0; j < 4; j++) {
                int ki = tx + 16 * j;
                float lo, hi;
                UNPACK2(lo, hi, s2[i][j]);
                float val = (lo + hi) * scale;
                if (diag && ki > qi) val = -1e30f;
                Ps[qi * PS_STRIDE + ki] = val;
            }
        }
        __syncthreads();

        {
            int q = tid >> 2;
            int cc = (tid & 3) * 16;
            float* pr = &Ps[q * PS_STRIDE + cc];
            float mx = -1e30f;
            #pragma unroll
            for (int c = 0; c < 16; c++) mx = fmaxf(mx, pr[c]);
            mx = fmaxf(mx, __shfl_xor_sync(0xffffffffu, mx, 1));
            mx = fmaxf(mx, __shfl_xor_sync(0xffffffffu, mx, 2));
            float m_new = fmaxf(m_r, mx);
            float al = __expf(m_r - m_new);
            float sum = 0.f;
            #pragma unroll
            for (int c = 0; c < 16; c++) {
                float p = __expf(pr[c] - m_new);
                pr[c] = p;
                sum += p;
            }
            sum += __shfl_xor_sync(0xffffffffu, sum, 1);
            sum += __shfl_xor_sync(0xffffffffu, sum, 2);
            l_r = l_r * al + sum;
            m_r = m_new;
            if ((tid & 3) == 0) { alpha_sh[q] = al; l_sh[q] = l_r; }
        }
        __syncthreads();

        #pragma unroll
        for (int i = 0; i < 4; i++) {
            float av = alpha_sh[ty + 16 * i];
            uint64_t avp; PACK2(avp, av, av);
            #pragma unroll
            for (int j = 0; j < 4; j++) { uint64_t t; MUL2(t, o2[i][j], avp); o2[i][j] = t; }
        }

        #pragma unroll 2
        for (int k = 0; k < 64; k++) {
            float p0 = Ps[(ty +  0) * PS_STRIDE + k];
            float p1 = Ps[(ty + 16) * PS_STRIDE + k];
            float p2 = Ps[(ty + 32) * PS_STRIDE + k];
            float p3 = Ps[(ty + 48) * PS_STRIDE + k];
            uint64_t pp0, pp1, pp2, pp3;
            PACK2(pp0, p0, p0); PACK2(pp1, p1, p1);
            PACK2(pp2, p2, p2); PACK2(pp3, p3, p3);
            float4 v0 = *(float4*)&Vs[k * VS_STRIDE + tx * 8];
            float4 v1 = *(float4*)&Vs[k * VS_STRIDE + tx * 8 + 4];
            uint64_t vv0, vv1, vv2, vv3;
            PACK2(vv0, v0.x, v0.y); PACK2(vv1, v0.z, v0.w);
            PACK2(vv2, v1.x, v1.y); PACK2(vv3, v1.z, v1.w);
            FMA2(o2[0][0], pp0, vv0); FMA2(o2[0][1], pp0, vv1); FMA2(o2[0][2], pp0, vv2); FMA2(o2[0][3], pp0, vv3);
            FMA2(o2[1][0], pp1, vv0); FMA2(o2[1][1], pp1, vv1); FMA2(o2[1][2], pp1, vv2); FMA2(o2[1][3], pp1, vv3);
            FMA2(o2[2][0], pp2, vv0); FMA2(o2[2][1], pp2, vv1); FMA2(o2[2][2], pp2, vv2); FMA2(o2[2][3], pp2, vv3);
            FMA2(o2[3][0], pp3, vv0); FMA2(o2[3][1], pp3, vv1); FMA2(o2[3][2], pp3, vv2); FMA2(o2[3][3], pp3, vv3);
        }
    }

    #pragma unroll
    for (int i = 0; i < 4; i++) {
        int qi = ty + 16 * i;
        float inv = 1.f / l_sh[qi];
        long long off = ((long long)(b * S_LEN + q0 + qi)) * E_DIM + h * D_HEAD + tx * 8;
        #pragma unroll
        for (int jp = 0; jp < 4; jp++) {
            float e0, e1;
            UNPACK2(e0, e1, o2[i][jp]);
            float v0 = e0 * inv;
            float v1 = e1 * inv;
            __half h0 = __float2half_rn(v0), h1 = __float2half_rn(v1);
            __half l0 = __float2half_rn(v0 - __half2float(h0));
            __half l1 = __float2half_rn(v1 - __half2float(h1));
            *(half2*)&ohi[off + jp * 2] = __halves2half2(h0, h1);
            *(half2*)&olo[off + jp * 2] = __halves2half2(l0, l1);
        }
    }
}

// ===========================================================================
extern "C" void kernel_launch(void* const* d_in, const int* in_sizes, int n_in,
                              void* d_out, int out_size)
{
    const float* hidden   = (const float*)d_in[0];
    const float* qkv_w    = (const float*)d_in[1];
    const float* o_w      = (const float*)d_in[2];
    const float* cosv     = (const float*)d_in[3];
    const float* sinv     = (const float*)d_in[4];
    const int*   blk_tab  = (const int*)d_in[7];

    float* out   = (float*)d_out;
    float* out_k = out + (size_t)T_TOK * E_DIM;
    float* out_v = out_k + (size_t)T_TOK * E_DIM;

    float*  qkv;  cudaGetSymbolAddress((void**)&qkv,  g_qkv);
    __half* wth;  cudaGetSymbolAddress((void**)&wth,  g_wt_hi);
    __half* wtl;  cudaGetSymbolAddress((void**)&wtl,  g_wt_lo);
    __half* ahi;  cudaGetSymbolAddress((void**)&ahi,  g_ahi);
    __half* alo;  cudaGetSymbolAddress((void**)&alo,  g_alo);

    // 0a) Transpose + split weights
    transpose_split_kernel<<<dim3(E_DIM / 32, E_DIM / 32, 4), dim3(32, 8)>>>(qkv_w, o_w, wth, wtl);
    // 0b) Split hidden activations
    {
        long long total = (long long)T_TOK * E_DIM / 4;
        split_a_kernel<<<(unsigned)((total + 255) / 256), 256>>>(hidden, ahi, alo);
    }

    // 1) QKV projection (fp16 split mma, f16-acc cross terms, 512 thr, occ 2)
    cudaFuncSetAttribute(gemm_mma_kernel, cudaFuncAttributeMaxDynamicSharedMemorySize, GEMM_SMEM);
    gemm_mma_kernel<<<dim3(E_DIM / 128, T_TOK / 128, 3), 512, GEMM_SMEM>>>(
        ahi, alo, wth, wtl, qkv, (long long)E_DIM * E_DIM, (long long)T_TOK * E_DIM);

    // 2) RoPE on q and k
    {
        long long total = 2LL * T_TOK * H_NUM * 64;
        rope_kernel<<<(unsigned)((total + 255) / 256), 256>>>(qkv, cosv, sinv);
    }

    // 3) KV cache scatter
    {
        long long total = (long long)B_SZ * NB_BLK * H_NUM * BS_BLK * D_HEAD;
        cache_write_kernel<<<(unsigned)((total + 255) / 256), 256>>>(qkv, blk_tab, out_k, out_v);
    }

    // 4) Flash attention (packed f32x2, hi/lo half output)
    {
        int smem = (64 * QS_STRIDE + 64 * KS_STRIDE + 64 * VS_STRIDE +
                    64 * PS_STRIDE + 64 + 64) * (int)sizeof(float);
        cudaFuncSetAttribute(attn_kernel, cudaFuncAttributeMaxDynamicSharedMemorySize, smem);
        attn_kernel<<<dim3(S_LEN / 64, H_NUM, B_SZ), 256, smem>>>(qkv, ahi, alo);
    }

    // 5) Output projection
    gemm_mma_kernel<<<dim3(E_DIM / 128, T_TOK / 128, 1), 512, GEMM_SMEM>>>(
        ahi, alo, wth + 3ULL * E_DIM * E_DIM, wtl + 3ULL * E_DIM * E_DIM, out, 0, 0);
}

// round 16
// speedup vs baseline: 2.0015x; 1.5494x over previous
#include <cuda_runtime.h>
#include <cuda_fp16.h>
#include <cstdint>

#define T_TOK 4096
#define E_DIM 4096
#define B_SZ  4
#define S_LEN 1024
#define H_NUM 32
#define D_HEAD 128
#define BS_BLK 16
#define NB_BLK 64

// Scratch (allocation-free rule: __device__ globals)
__device__ float  g_qkv[3ULL * T_TOK * E_DIM];        // q | k | v fp32
__device__ __half g_wt_hi[4ULL * E_DIM * E_DIM];      // transposed weight hi planes [4][N][K]
__device__ __half g_wt_lo[4ULL * E_DIM * E_DIM];      // transposed weight lo planes
__device__ __half g_ahi[(size_t)T_TOK * E_DIM];       // activation hi plane [T, E]
__device__ __half g_alo[(size_t)T_TOK * E_DIM];       // activation lo plane

// ===========================================================================
// helpers
// ===========================================================================
__device__ __forceinline__ uint32_t smem_u32(const void* p) {
    uint32_t a;
    asm("{ .reg .u64 t; cvta.to.shared.u64 t, %1; cvt.u32.u64 %0, t; }" : "=r"(a) : "l"(p));
    return a;
}
__device__ __forceinline__ void cp16(uint32_t dst, const void* src) {
    asm volatile("cp.async.ca.shared.global [%0], [%1], 16;" :: "r"(dst), "l"(src));
}
#define CP_COMMIT() asm volatile("cp.async.commit_group;" ::: "memory")
#define CP_WAIT1()  asm volatile("cp.async.wait_group 1;" ::: "memory")

__device__ __forceinline__ void mma_f16(float* c, const uint32_t* a, const uint32_t* b) {
    asm volatile(
        "mma.sync.aligned.m16n8k16.row.col.f32.f16.f16.f32 "
        "{%0,%1,%2,%3}, {%4,%5,%6,%7}, {%8,%9}, {%0,%1,%2,%3};"
        : "+f"(c[0]), "+f"(c[1]), "+f"(c[2]), "+f"(c[3])
        : "r"(a[0]), "r"(a[1]), "r"(a[2]), "r"(a[3]), "r"(b[0]), "r"(b[1]));
}
__device__ __forceinline__ void ldmatrix_x4(uint32_t* r, uint32_t addr) {
    asm volatile("ldmatrix.sync.aligned.m8n8.x4.shared.b16 {%0,%1,%2,%3}, [%4];"
                 : "=r"(r[0]), "=r"(r[1]), "=r"(r[2]), "=r"(r[3]) : "r"(addr));
}

// Packed fp32x2 ops (Blackwell)
#define FMA2(acc, a, b) \
    asm("fma.rn.f32x2 %0, %1, %2, %0;" : "+l"(acc) : "l"(a), "l"(b))
#define MUL2(out, a, b) \
    asm("mul.rn.f32x2 %0, %1, %2;" : "=l"(out) : "l"(a), "l"(b))
#define PACK2(out, lo, hi) \
    asm("mov.b64 %0, {%1, %2};" : "=l"(out) : "f"(lo), "f"(hi))
#define UNPACK2(lo, hi, in) \
    asm("mov.b64 {%0, %1}, %2;" : "=f"(lo), "=f"(hi) : "l"(in))

// ===========================================================================
// Weight transpose + hi/lo split: W[z][k][n] fp32 -> Wt_hi/lo[z][n][k] half
// ===========================================================================
__global__ void transpose_split_kernel(const float* __restrict__ qkv_w,
                                       const float* __restrict__ o_w,
                                       __half* __restrict__ out_hi,
                                       __half* __restrict__ out_lo)
{
    __shared__ float tile[32][33];
    int z = blockIdx.z;
    const float* src = (z < 3) ? qkv_w + (size_t)z * E_DIM * E_DIM : o_w;
    __half* dhi = out_hi + (size_t)z * E_DIM * E_DIM;
    __half* dlo = out_lo + (size_t)z * E_DIM * E_DIM;
    int k0 = blockIdx.y * 32, n0 = blockIdx.x * 32;
    int tx = threadIdx.x, ty = threadIdx.y;
    #pragma unroll
    for (int j = 0; j < 32; j += 8)
        tile[ty + j][tx] = src[(size_t)(k0 + ty + j) * E_DIM + n0 + tx];
    __syncthreads();
    #pragma unroll
    for (int j = 0; j < 32; j += 8) {
        float x = tile[tx][ty + j];
        __half hi = __float2half_rn(x);
        __half lo = __float2half_rn(x - __half2float(hi));
        size_t off = (size_t)(n0 + ty + j) * E_DIM + k0 + tx;
        dhi[off] = hi;
        dlo[off] = lo;
    }
}

// ===========================================================================
// Activation hi/lo split: X[T,E] fp32 -> hi/lo half planes
// ===========================================================================
__global__ void split_a_kernel(const float* __restrict__ x,
                               __half* __restrict__ xhi, __half* __restrict__ xlo)
{
    long long i = ((long long)blockIdx.x * blockDim.x + threadIdx.x) * 4;
    if (i >= (long long)T_TOK * E_DIM) return;
    float4 v = *(const float4*)&x[i];
    __half h0 = __float2half_rn(v.x), h1 = __float2half_rn(v.y);
    __half h2 = __float2half_rn(v.z), h3 = __float2half_rn(v.w);
    __half l0 = __float2half_rn(v.x - __half2float(h0));
    __half l1 = __float2half_rn(v.y - __half2float(h1));
    __half l2 = __float2half_rn(v.z - __half2float(h2));
    __half l3 = __float2half_rn(v.w - __half2float(h3));
    *(half2*)&xhi[i]     = __halves2half2(h0, h1);
    *(half2*)&xhi[i + 2] = __halves2half2(h2, h3);
    *(half2*)&xlo[i]     = __halves2half2(l0, l1);
    *(half2*)&xlo[i + 2] = __halves2half2(l2, l3);
}

// ===========================================================================
// fp16 hi/lo split GEMM with ldmatrix (R13 compute config, 3-stage pipeline)
// Block tile 128x128, K-tile 16, 8 warps (2Mx4N), warp tile 64x32.
// Row layout per stage: 128 rows x 80B (hi 32B | lo 32B | 16B pad) per matrix.
// 3-stage cp.async ring, wait_group 1 -> barrier, 2 CTAs/SM.
// ===========================================================================
#define KT 16
#define NK_ITERS (E_DIM / KT)              // 256
#define ROW_B 80
#define TILE_B (128 * ROW_B)               // 10240
#define STAGE_B (2 * TILE_B)               // 20480
#define NSTAGES 3
#define GEMM_SMEM (NSTAGES * STAGE_B)      // 61440

__device__ __forceinline__ void stage_load(uint32_t smb, int st,
                                           const __half* __restrict__ Ahi,
                                           const __half* __restrict__ Alo,
                                           const __half* __restrict__ Bhi,
                                           const __half* __restrict__ Blo,
                                           int k0, int tid)
{
    #pragma unroll
    for (int j = 0; j < 4; ++j) {
        int idx = tid + 256 * j;
        int m   = idx >> 9;
        int r   = (idx >> 2) & 127;
        int seg = idx & 3;                 // 0,1 = hi halves ; 2,3 = lo halves
        uint32_t dst = smb + st * STAGE_B + m * TILE_B + r * ROW_B + seg * 16;
        const __half* hp = m ? Bhi : Ahi;
        const __half* lp = m ? Blo : Alo;
        const __half* src = (seg < 2 ? hp : lp) + (long long)r * E_DIM + k0 + (seg & 1) * 8;
        cp16(dst, src);
    }
}

__global__ __launch_bounds__(256, 2)
void gemm_mma_kernel(const __half* __restrict__ Ahi, const __half* __restrict__ Alo,
                     const __half* __restrict__ Bhi, const __half* __restrict__ Blo,
                     float* __restrict__ C, long long strideB, long long strideC)
{
    extern __shared__ char sm[];
    uint32_t smb = smem_u32(sm);
    const int tid = threadIdx.x;
    const int wid = tid >> 5;
    const int lane = tid & 31;
    const int grp = lane >> 2;
    const int thr = lane & 3;
    const int warp_m = wid >> 2;
    const int warp_n = wid & 3;

    const int m0 = blockIdx.y * 128;
    const int n0 = blockIdx.x * 128;
    const __half* Ah = Ahi + (long long)m0 * E_DIM;
    const __half* Al = Alo + (long long)m0 * E_DIM;
    const __half* Bh = Bhi + (long long)blockIdx.z * strideB + (long long)n0 * E_DIM;
    const __half* Bl = Blo + (long long)blockIdx.z * strideB + (long long)n0 * E_DIM;
    float* Cg = C + (long long)blockIdx.z * strideC;

    float acc[4][4][4];
    #pragma unroll
    for (int mi = 0; mi < 4; mi++)
        #pragma unroll
        for (int ni = 0; ni < 4; ni++)
            #pragma unroll
            for (int q = 0; q < 4; q++) acc[mi][ni][q] = 0.f;

    const uint32_t a_lane_off =
        (uint32_t)((warp_m * 64 + (lane & 15)) * ROW_B + (lane >> 4) * 16);
    const uint32_t b_lane_off =
        (uint32_t)((warp_n * 32 + (lane >> 4) * 8 + (lane & 7)) * ROW_B + ((lane >> 3) & 1) * 16);

    // prologue: stages 0, 1
    stage_load(smb, 0, Ah, Al, Bh, Bl, 0, tid);   CP_COMMIT();
    stage_load(smb, 1, Ah, Al, Bh, Bl, KT, tid);  CP_COMMIT();

    int st = 0;
    for (int kt = 0; kt < NK_ITERS; ++kt) {
        CP_WAIT1();        // load(kt) done (this thread); load(kt+1) may be in flight
        __syncthreads();   // publish load(kt); reads of stage (kt+2)%3 (from kt-1) retired

        if (kt + 2 < NK_ITERS) {
            int nst = st + 2; if (nst >= NSTAGES) nst -= NSTAGES;
            stage_load(smb, nst, Ah, Al, Bh, Bl, (kt + 2) * KT, tid);
            CP_COMMIT();
        }

        uint32_t abase = smb + st * STAGE_B + a_lane_off;
        uint32_t bbase = smb + st * STAGE_B + TILE_B + b_lane_off;

        uint32_t ah[4][4], al[4][4];
        #pragma unroll
        for (int mi = 0; mi < 4; mi++) {
            ldmatrix_x4(ah[mi], abase + mi * 16 * ROW_B);
            ldmatrix_x4(al[mi], abase + mi * 16 * ROW_B + 32);
        }
        #pragma unroll
        for (int g = 0; g < 2; g++) {
            uint32_t bh[4], bl[4];
            ldmatrix_x4(bh, bbase + g * 16 * ROW_B);
            ldmatrix_x4(bl, bbase + g * 16 * ROW_B + 32);
            #pragma unroll
            for (int mi = 0; mi < 4; mi++)
                #pragma unroll
                for (int nj = 0; nj < 2; nj++) {
                    float* accp = acc[mi][g * 2 + nj];
                    mma_f16(accp, al[mi], &bh[nj * 2]);
                    mma_f16(accp, ah[mi], &bl[nj * 2]);
                    mma_f16(accp, ah[mi], &bh[nj * 2]);
                }
        }
        st = st + 1; if (st >= NSTAGES) st = 0;
    }

    // epilogue: direct global stores
    #pragma unroll
    for (int mi = 0; mi < 4; mi++) {
        long long r0 = m0 + warp_m * 64 + mi * 16 + grp;
        #pragma unroll
        for (int ni = 0; ni < 4; ni++) {
            long long col = n0 + warp_n * 32 + ni * 8 + thr * 2;
            *(float2*)&Cg[r0 * E_DIM + col]       = make_float2(acc[mi][ni][0], acc[mi][ni][1]);
            *(float2*)&Cg[(r0 + 8) * E_DIM + col] = make_float2(acc[mi][ni][2], acc[mi][ni][3]);
        }
    }
}

// ===========================================================================
// Fused RoPE + KV cache scatter.
// idx over T*H*64 pairs: rope q (in place), rope k (in place + scatter to
// k_cache), copy v pair to v_cache. One pass over q,k,v.
// ===========================================================================
__global__ void rope_cache_kernel(float* __restrict__ qkv,
                                  const float* __restrict__ cosv,
                                  const float* __restrict__ sinv,
                                  const int* __restrict__ block_tables,
                                  float* __restrict__ out_k,
                                  float* __restrict__ out_v)
{
    long long idx = (long long)blockIdx.x * blockDim.x + threadIdx.x;
    if (idx >= (long long)T_TOK * H_NUM * 64) return;
    int j = idx & 63;
    int h = (idx >> 6) & (H_NUM - 1);
    long long t = idx >> 11;

    float c = cosv[t * 64 + j];
    float s = sinv[t * 64 + j];

    // rope q in place
    float* qp = g_qkv + t * E_DIM + h * D_HEAD;
    float q1 = qp[j], q2 = qp[j + 64];
    qp[j]      = q1 * c - q2 * s;
    qp[j + 64] = q2 * c + q1 * s;

    // rope k in place + scatter
    float* kp = g_qkv + (long long)T_TOK * E_DIM + t * E_DIM + h * D_HEAD;
    float k1 = kp[j], k2 = kp[j + 64];
    float kr1 = k1 * c - k2 * s;
    float kr2 = k2 * c + k1 * s;
    kp[j]      = kr1;
    kp[j + 64] = kr2;

    int b  = (int)(t >> 10);
    int nb = (int)((t >> 4) & 63);
    int bs = (int)(t & 15);
    int blk = block_tables[b * NB_BLK + nb];
    long long cdst = (((long long)blk * H_NUM + h) * BS_BLK + bs) * D_HEAD;
    out_k[cdst + j]      = kr1;
    out_k[cdst + j + 64] = kr2;

    // v scatter (no rope)
    const float* vp = g_qkv + 2LL * T_TOK * E_DIM + t * E_DIM + h * D_HEAD;
    out_v[cdst + j]      = vp[j];
    out_v[cdst + j + 64] = vp[j + 64];
}

// ===========================================================================
// Flash attention, fp32 with packed f32x2 FMA, causal.
// Writes hi/lo half planes for the O-proj GEMM. (R13 version, unchanged.)
// ===========================================================================
#define QS_STRIDE 130
#define KS_STRIDE 130
#define VS_STRIDE 132
#define PS_STRIDE 65

__global__ __launch_bounds__(256, 1)
void attn_kernel(const float* __restrict__ qkv,
                 __half* __restrict__ ohi, __half* __restrict__ olo)
{
    extern __shared__ float smf[];
    float* Qs = smf;
    float* Ks = Qs + 64 * QS_STRIDE;
    float* Vs = Ks + 64 * KS_STRIDE;
    float* Ps = Vs + 64 * VS_STRIDE;
    float* alpha_sh = Ps + 64 * PS_STRIDE;
    float* l_sh = alpha_sh + 64;

    int tid = threadIdx.x;
    int tx = tid & 15, ty = tid >> 4;
    int qt = blockIdx.x, h = blockIdx.y, b = blockIdx.z;
    int q0 = qt * 64;

    const long long TE = (long long)T_TOK * E_DIM;
    const float* qbase = qkv;
    const float* kbase = qkv + TE;
    const float* vbase = qkv + 2 * TE;
    const float scale = 0.08838834764831845f;

    for (int c = tid; c < 64 * 32; c += 256) {
        int row = c >> 5;
        int c4 = (c & 31) * 4;
        float4 v = *(const float4*)&qbase[((long long)(b * S_LEN + q0 + row)) * E_DIM + h * D_HEAD + c4];
        *(float2*)&Qs[row * QS_STRIDE + c4]     = make_float2(v.x, v.y);
        *(float2*)&Qs[row * QS_STRIDE + c4 + 2] = make_float2(v.z, v.w);
    }

    float m_r = -1e30f, l_r = 0.f;
    uint64_t o2[4][4];
    #pragma unroll
    for (int i = 0; i < 4; i++)
        #pragma unroll
        for (int j = 0; j < 4; j++) o2[i][j] = 0ull;

    int nkt = qt + 1;
    for (int kt = 0; kt < nkt; kt++) {
        int k0 = kt * 64;
        __syncthreads();
        for (int c = tid; c < 64 * 32; c += 256) {
            int row = c >> 5;
            int c4 = (c & 31) * 4;
            long long goff = ((long long)(b * S_LEN + k0 + row)) * E_DIM + h * D_HEAD + c4;
            float4 kv = *(const float4*)&kbase[goff];
            *(float2*)&Ks[row * KS_STRIDE + c4]     = make_float2(kv.x, kv.y);
            *(float2*)&Ks[row * KS_STRIDE + c4 + 2] = make_float2(kv.z, kv.w);
            float4 vv = *(const float4*)&vbase[goff];
            *(float4*)&Vs[row * VS_STRIDE + c4] = vv;
        }
        __syncthreads();

        uint64_t s2[4][4];
        #pragma unroll
        for (int i = 0; i < 4; i++)
            #pragma unroll
            for (int j = 0; j < 4; j++) s2[i][j] = 0ull;
        const float* qr0 = &Qs[(ty +  0) * QS_STRIDE];
        const float* qr1 = &Qs[(ty + 16) * QS_STRIDE];
        const float* qr2 = &Qs[(ty + 32) * QS_STRIDE];
        const float* qr3 = &Qs[(ty + 48) * QS_STRIDE];
        const float* kr0 = &Ks[(tx +  0) * KS_STRIDE];
        const float* kr1 = &Ks[(tx + 16) * KS_STRIDE];
        const float* kr2 = &Ks[(tx + 32) * KS_STRIDE];
        const float* kr3 = &Ks[(tx + 48) * KS_STRIDE];
        #pragma unroll 4
        for (int d = 0; d < 128; d += 2) {
            uint64_t a0 = *(const uint64_t*)(qr0 + d);
            uint64_t a1 = *(const uint64_t*)(qr1 + d);
            uint64_t a2 = *(const uint64_t*)(qr2 + d);
            uint64_t a3 = *(const uint64_t*)(qr3 + d);
            uint64_t b0 = *(const uint64_t*)(kr0 + d);
            uint64_t b1 = *(const uint64_t*)(kr1 + d);
            uint64_t b2 = *(const uint64_t*)(kr2 + d);
            uint64_t b3 = *(const uint64_t*)(kr3 + d);
            FMA2(s2[0][0], a0, b0); FMA2(s2[0][1], a0, b1); FMA2(s2[0][2], a0, b2); FMA2(s2[0][3], a0, b3);
            FMA2(s2[1][0], a1, b0); FMA2(s2[1][1], a1, b1); FMA2(s2[1][2], a1, b2); FMA2(s2[1][3], a1, b3);
            FMA2(s2[2][0], a2, b0); FMA2(s2[2][1], a2, b1); FMA2(s2[2][2], a2, b2); FMA2(s2[2][3], a2, b3);
            FMA2(s2[3][0], a3, b0); FMA2(s2[3][1], a3, b1); FMA2(s2[3][2], a3, b2); FMA2(s2[3][3], a3, b3);
        }
        bool diag = (kt == qt);
        #pragma unroll
        for (int i = 0; i < 4; i++) {
            int qi = ty + 16 * i;
            #pragma unroll
            for (int j = 0; j < 4; j++) {
                int ki = tx + 16 * j;
                float lo, hi;
                UNPACK2(lo, hi, s2[i][j]);
                float val = (lo + hi) * scale;
                if (diag && ki > qi) val = -1e30f;
                Ps[qi * PS_STRIDE + ki] = val;
            }
        }
        __syncthreads();

        {
            int q = tid >> 2;
            int cc = (tid & 3) * 16;
            float* pr = &Ps[q * PS_STRIDE + cc];
            float mx = -1e30f;
            #pragma unroll
            for (int c = 0; c < 16; c++) mx = fmaxf(mx, pr[c]);
            mx = fmaxf(mx, __shfl_xor_sync(0xffffffffu, mx, 1));
            mx = fmaxf(mx, __shfl_xor_sync(0xffffffffu, mx, 2));
            float m_new = fmaxf(m_r, mx);
            float al = __expf(m_r - m_new);
            float sum = 0.f;
            #pragma unroll
            for (int c = 0; c < 16; c++) {
                float p = __expf(pr[c] - m_new);
                pr[c] = p;
                sum += p;
            }
            sum += __shfl_xor_sync(0xffffffffu, sum, 1);
            sum += __shfl_xor_sync(0xffffffffu, sum, 2);
            l_r = l_r * al + sum;
            m_r = m_new;
            if ((tid & 3) == 0) { alpha_sh[q] = al; l_sh[q] = l_r; }
        }
        __syncthreads();

        #pragma unroll
        for (int i = 0; i < 4; i++) {
            float av = alpha_sh[ty + 16 * i];
            uint64_t avp; PACK2(avp, av, av);
            #pragma unroll
            for (int j = 0; j < 4; j++) { uint64_t t; MUL2(t, o2[i][j], avp); o2[i][j] = t; }
        }

        #pragma unroll 2
        for (int k = 0; k < 64; k++) {
            float p0 = Ps[(ty +  0) * PS_STRIDE + k];
            float p1 = Ps[(ty + 16) * PS_STRIDE + k];
            float p2 = Ps[(ty + 32) * PS_STRIDE + k];
            float p3 = Ps[(ty + 48) * PS_STRIDE + k];
            uint64_t pp0, pp1, pp2, pp3;
            PACK2(pp0, p0, p0); PACK2(pp1, p1, p1);
            PACK2(pp2, p2, p2); PACK2(pp3, p3, p3);
            float4 v0 = *(float4*)&Vs[k * VS_STRIDE + tx * 8];
            float4 v1 = *(float4*)&Vs[k * VS_STRIDE + tx * 8 + 4];
            uint64_t vv0, vv1, vv2, vv3;
            PACK2(vv0, v0.x, v0.y); PACK2(vv1, v0.z, v0.w);
            PACK2(vv2, v1.x, v1.y); PACK2(vv3, v1.z, v1.w);
            FMA2(o2[0][0], pp0, vv0); FMA2(o2[0][1], pp0, vv1); FMA2(o2[0][2], pp0, vv2); FMA2(o2[0][3], pp0, vv3);
            FMA2(o2[1][0], pp1, vv0); FMA2(o2[1][1], pp1, vv1); FMA2(o2[1][2], pp1, vv2); FMA2(o2[1][3], pp1, vv3);
            FMA2(o2[2][0], pp2, vv0); FMA2(o2[2][1], pp2, vv1); FMA2(o2[2][2], pp2, vv2); FMA2(o2[2][3], pp2, vv3);
            FMA2(o2[3][0], pp3, vv0); FMA2(o2[3][1], pp3, vv1); FMA2(o2[3][2], pp3, vv2); FMA2(o2[3][3], pp3, vv3);
        }
    }

    #pragma unroll
    for (int i = 0; i < 4; i++) {
        int qi = ty + 16 * i;
        float inv = 1.f / l_sh[qi];
        long long off = ((long long)(b * S_LEN + q0 + qi)) * E_DIM + h * D_HEAD + tx * 8;
        #pragma unroll
        for (int jp = 0; jp < 4; jp++) {
            float e0, e1;
            UNPACK2(e0, e1, o2[i][jp]);
            float v0 = e0 * inv;
            float v1 = e1 * inv;
            __half h0 = __float2half_rn(v0), h1 = __float2half_rn(v1);
            __half l0 = __float2half_rn(v0 - __half2float(h0));
            __half l1 = __float2half_rn(v1 - __half2float(h1));
            *(half2*)&ohi[off + jp * 2] = __halves2half2(h0, h1);
            *(half2*)&olo[off + jp * 2] = __halves2half2(l0, l1);
        }
    }
}

// ===========================================================================
extern "C" void kernel_launch(void* const* d_in, const int* in_sizes, int n_in,
                              void* d_out, int out_size)
{
    const float* hidden   = (const float*)d_in[0];
    const float* qkv_w    = (const float*)d_in[1];
    const float* o_w      = (const float*)d_in[2];
    const float* cosv     = (const float*)d_in[3];
    const float* sinv     = (const float*)d_in[4];
    const int*   blk_tab  = (const int*)d_in[7];

    float* out   = (float*)d_out;
    float* out_k = out + (size_t)T_TOK * E_DIM;
    float* out_v = out_k + (size_t)T_TOK * E_DIM;

    float*  qkv;  cudaGetSymbolAddress((void**)&qkv,  g_qkv);
    __half* wth;  cudaGetSymbolAddress((void**)&wth,  g_wt_hi);
    __half* wtl;  cudaGetSymbolAddress((void**)&wtl,  g_wt_lo);
    __half* ahi;  cudaGetSymbolAddress((void**)&ahi,  g_ahi);
    __half* alo;  cudaGetSymbolAddress((void**)&alo,  g_alo);

    // 0a) Transpose + split weights
    transpose_split_kernel<<<dim3(E_DIM / 32, E_DIM / 32, 4), dim3(32, 8)>>>(qkv_w, o_w, wth, wtl);
    // 0b) Split hidden activations
    {
        long long total = (long long)T_TOK * E_DIM / 4;
        split_a_kernel<<<(unsigned)((total + 255) / 256), 256>>>(hidden, ahi, alo);
    }

    // 1) QKV projection (fp16 split mma + ldmatrix, 3-stage, occ 2)
    cudaFuncSetAttribute(gemm_mma_kernel, cudaFuncAttributeMaxDynamicSharedMemorySize, GEMM_SMEM);
    gemm_mma_kernel<<<dim3(E_DIM / 128, T_TOK / 128, 3), 256, GEMM_SMEM>>>(
        ahi, alo, wth, wtl, qkv, (long long)E_DIM * E_DIM, (long long)T_TOK * E_DIM);

    // 2) Fused RoPE + KV cache scatter
    {
        long long total = (long long)T_TOK * H_NUM * 64;
        rope_cache_kernel<<<(unsigned)((total + 255) / 256), 256>>>(
            qkv, cosv, sinv, blk_tab, out_k, out_v);
    }

    // 3) Flash attention (packed f32x2, hi/lo half output)
    {
        int smem = (64 * QS_STRIDE + 64 * KS_STRIDE + 64 * VS_STRIDE +
                    64 * PS_STRIDE + 64 + 64) * (int)sizeof(float);
        cudaFuncSetAttribute(attn_kernel, cudaFuncAttributeMaxDynamicSharedMemorySize, smem);
        attn_kernel<<<dim3(S_LEN / 64, H_NUM, B_SZ), 256, smem>>>(qkv, ahi, alo);
    }

    // 4) Output projection
    gemm_mma_kernel<<<dim3(E_DIM / 128, T_TOK / 128, 1), 256, GEMM_SMEM>>>(
        ahi, alo, wth + 3ULL * E_DIM * E_DIM, wtl + 3ULL * E_DIM * E_DIM, out, 0, 0);
}

// round 17
// speedup vs baseline: 2.0812x; 1.0398x over previous
#include <cuda_runtime.h>
#include <cuda_fp16.h>
#include <cstdint>

#define T_TOK 4096
#define E_DIM 4096
#define B_SZ  4
#define S_LEN 1024
#define H_NUM 32
#define D_HEAD 128
#define BS_BLK 16
#define NB_BLK 64

// Scratch (allocation-free rule: __device__ globals)
__device__ float  g_qkv[3ULL * T_TOK * E_DIM];        // q | k | v fp32
__device__ __half g_wt_hi[4ULL * E_DIM * E_DIM];      // transposed weight hi planes [4][N][K]
__device__ __half g_wt_lo[4ULL * E_DIM * E_DIM];      // transposed weight lo planes
__device__ __half g_ahi[(size_t)T_TOK * E_DIM];       // activation hi plane [T, E]
__device__ __half g_alo[(size_t)T_TOK * E_DIM];       // activation lo plane

// ===========================================================================
// helpers
// ===========================================================================
__device__ __forceinline__ uint32_t smem_u32(const void* p) {
    uint32_t a;
    asm("{ .reg .u64 t; cvta.to.shared.u64 t, %1; cvt.u32.u64 %0, t; }" : "=r"(a) : "l"(p));
    return a;
}
__device__ __forceinline__ void cp16(uint32_t dst, const void* src) {
    asm volatile("cp.async.ca.shared.global [%0], [%1], 16;" :: "r"(dst), "l"(src));
}
#define CP_COMMIT() asm volatile("cp.async.commit_group;" ::: "memory")
#define CP_WAIT0()  asm volatile("cp.async.wait_group 0;" ::: "memory")

__device__ __forceinline__ void mma_f16(float* c, const uint32_t* a, const uint32_t* b) {
    asm volatile(
        "mma.sync.aligned.m16n8k16.row.col.f32.f16.f16.f32 "
        "{%0,%1,%2,%3}, {%4,%5,%6,%7}, {%8,%9}, {%0,%1,%2,%3};"
        : "+f"(c[0]), "+f"(c[1]), "+f"(c[2]), "+f"(c[3])
        : "r"(a[0]), "r"(a[1]), "r"(a[2]), "r"(a[3]), "r"(b[0]), "r"(b[1]));
}
__device__ __forceinline__ void ldmatrix_x4(uint32_t* r, uint32_t addr) {
    asm volatile("ldmatrix.sync.aligned.m8n8.x4.shared.b16 {%0,%1,%2,%3}, [%4];"
                 : "=r"(r[0]), "=r"(r[1]), "=r"(r[2]), "=r"(r[3]) : "r"(addr));
}

// Packed fp32x2 ops (Blackwell)
#define FMA2(acc, a, b) \
    asm("fma.rn.f32x2 %0, %1, %2, %0;" : "+l"(acc) : "l"(a), "l"(b))
#define MUL2(out, a, b) \
    asm("mul.rn.f32x2 %0, %1, %2;" : "=l"(out) : "l"(a), "l"(b))
#define PACK2(out, lo, hi) \
    asm("mov.b64 %0, {%1, %2};" : "=l"(out) : "f"(lo), "f"(hi))
#define UNPACK2(lo, hi, in) \
    asm("mov.b64 {%0, %1}, %2;" : "=f"(lo), "=f"(hi) : "l"(in))

// ===========================================================================
// Weight transpose + hi/lo split: W[z][k][n] fp32 -> Wt_hi/lo[z][n][k] half
// ===========================================================================
__global__ void transpose_split_kernel(const float* __restrict__ qkv_w,
                                       const float* __restrict__ o_w,
                                       __half* __restrict__ out_hi,
                                       __half* __restrict__ out_lo)
{
    __shared__ float tile[32][33];
    int z = blockIdx.z;
    const float* src = (z < 3) ? qkv_w + (size_t)z * E_DIM * E_DIM : o_w;
    __half* dhi = out_hi + (size_t)z * E_DIM * E_DIM;
    __half* dlo = out_lo + (size_t)z * E_DIM * E_DIM;
    int k0 = blockIdx.y * 32, n0 = blockIdx.x * 32;
    int tx = threadIdx.x, ty = threadIdx.y;
    #pragma unroll
    for (int j = 0; j < 32; j += 8)
        tile[ty + j][tx] = src[(size_t)(k0 + ty + j) * E_DIM + n0 + tx];
    __syncthreads();
    #pragma unroll
    for (int j = 0; j < 32; j += 8) {
        float x = tile[tx][ty + j];
        __half hi = __float2half_rn(x);
        __half lo = __float2half_rn(x - __half2float(hi));
        size_t off = (size_t)(n0 + ty + j) * E_DIM + k0 + tx;
        dhi[off] = hi;
        dlo[off] = lo;
    }
}

// ===========================================================================
// Activation hi/lo split: X[T,E] fp32 -> hi/lo half planes
// ===========================================================================
__global__ void split_a_kernel(const float* __restrict__ x,
                               __half* __restrict__ xhi, __half* __restrict__ xlo)
{
    long long i = ((long long)blockIdx.x * blockDim.x + threadIdx.x) * 4;
    if (i >= (long long)T_TOK * E_DIM) return;
    float4 v = *(const float4*)&x[i];
    __half h0 = __float2half_rn(v.x), h1 = __float2half_rn(v.y);
    __half h2 = __float2half_rn(v.z), h3 = __float2half_rn(v.w);
    __half l0 = __float2half_rn(v.x - __half2float(h0));
    __half l1 = __float2half_rn(v.y - __half2float(h1));
    __half l2 = __float2half_rn(v.z - __half2float(h2));
    __half l3 = __float2half_rn(v.w - __half2float(h3));
    *(half2*)&xhi[i]     = __halves2half2(h0, h1);
    *(half2*)&xhi[i + 2] = __halves2half2(h2, h3);
    *(half2*)&xlo[i]     = __halves2half2(l0, l1);
    *(half2*)&xlo[i + 2] = __halves2half2(l2, l3);
}

// ===========================================================================
// fp16 hi/lo split GEMM with ldmatrix (exact R13 winner)
// Block tile 128x128, K-tile 16, 8 warps (2Mx4N), warp tile 64x32.
// Row layout per stage: 128 rows x 80B (hi 32B | lo 32B | 16B pad) per matrix.
// 2-stage cp.async double buffer, wait0 THEN barrier, 2 CTAs/SM.
// ===========================================================================
#define KT 16
#define NK_ITERS (E_DIM / KT)              // 256
#define ROW_B 80
#define TILE_B (128 * ROW_B)               // 10240
#define STAGE_B (2 * TILE_B)               // 20480
#define GEMM_SMEM (2 * STAGE_B)            // 40960

__device__ __forceinline__ void stage_load(uint32_t smb, int st,
                                           const __half* __restrict__ Ahi,
                                           const __half* __restrict__ Alo,
                                           const __half* __restrict__ Bhi,
                                           const __half* __restrict__ Blo,
                                           int k0, int tid)
{
    #pragma unroll
    for (int j = 0; j < 4; ++j) {
        int idx = tid + 256 * j;
        int m   = idx >> 9;
        int r   = (idx >> 2) & 127;
        int seg = idx & 3;                 // 0,1 = hi halves ; 2,3 = lo halves
        uint32_t dst = smb + st * STAGE_B + m * TILE_B + r * ROW_B + seg * 16;
        const __half* hp = m ? Bhi : Ahi;
        const __half* lp = m ? Blo : Alo;
        const __half* src = (seg < 2 ? hp : lp) + (long long)r * E_DIM + k0 + (seg & 1) * 8;
        cp16(dst, src);
    }
}

__global__ __launch_bounds__(256, 2)
void gemm_mma_kernel(const __half* __restrict__ Ahi, const __half* __restrict__ Alo,
                     const __half* __restrict__ Bhi, const __half* __restrict__ Blo,
                     float* __restrict__ C, long long strideB, long long strideC)
{
    extern __shared__ char sm[];
    uint32_t smb = smem_u32(sm);
    const int tid = threadIdx.x;
    const int wid = tid >> 5;
    const int lane = tid & 31;
    const int grp = lane >> 2;
    const int thr = lane & 3;
    const int warp_m = wid >> 2;
    const int warp_n = wid & 3;

    const int m0 = blockIdx.y * 128;
    const int n0 = blockIdx.x * 128;
    const __half* Ah = Ahi + (long long)m0 * E_DIM;
    const __half* Al = Alo + (long long)m0 * E_DIM;
    const __half* Bh = Bhi + (long long)blockIdx.z * strideB + (long long)n0 * E_DIM;
    const __half* Bl = Blo + (long long)blockIdx.z * strideB + (long long)n0 * E_DIM;
    float* Cg = C + (long long)blockIdx.z * strideC;

    float acc[4][4][4];
    #pragma unroll
    for (int mi = 0; mi < 4; mi++)
        #pragma unroll
        for (int ni = 0; ni < 4; ni++)
            #pragma unroll
            for (int q = 0; q < 4; q++) acc[mi][ni][q] = 0.f;

    const uint32_t a_lane_off =
        (uint32_t)((warp_m * 64 + (lane & 15)) * ROW_B + (lane >> 4) * 16);
    const uint32_t b_lane_off =
        (uint32_t)((warp_n * 32 + (lane >> 4) * 8 + (lane & 7)) * ROW_B + ((lane >> 3) & 1) * 16);

    stage_load(smb, 0, Ah, Al, Bh, Bl, 0, tid);
    CP_COMMIT();

    for (int kt = 0; kt < NK_ITERS; ++kt) {
        int st = kt & 1;
        CP_WAIT0();        // load(kt) complete (this thread's copies)
        __syncthreads();   // ...visible to all warps; buf^1 reads from kt-1 retired

        if (kt + 1 < NK_ITERS) {
            stage_load(smb, (kt + 1) & 1, Ah, Al, Bh, Bl, (kt + 1) * KT, tid);
            CP_COMMIT();
        }

        uint32_t abase = smb + st * STAGE_B + a_lane_off;
        uint32_t bbase = smb + st * STAGE_B + TILE_B + b_lane_off;

        uint32_t ah[4][4], al[4][4];
        #pragma unroll
        for (int mi = 0; mi < 4; mi++) {
            ldmatrix_x4(ah[mi], abase + mi * 16 * ROW_B);
            ldmatrix_x4(al[mi], abase + mi * 16 * ROW_B + 32);
        }
        #pragma unroll
        for (int g = 0; g < 2; g++) {
            uint32_t bh[4], bl[4];
            ldmatrix_x4(bh, bbase + g * 16 * ROW_B);
            ldmatrix_x4(bl, bbase + g * 16 * ROW_B + 32);
            #pragma unroll
            for (int mi = 0; mi < 4; mi++)
                #pragma unroll
                for (int nj = 0; nj < 2; nj++) {
                    float* accp = acc[mi][g * 2 + nj];
                    mma_f16(accp, al[mi], &bh[nj * 2]);
                    mma_f16(accp, ah[mi], &bl[nj * 2]);
                    mma_f16(accp, ah[mi], &bh[nj * 2]);
                }
        }
    }

    // epilogue: direct global stores
    #pragma unroll
    for (int mi = 0; mi < 4; mi++) {
        long long r0 = m0 + warp_m * 64 + mi * 16 + grp;
        #pragma unroll
        for (int ni = 0; ni < 4; ni++) {
            long long col = n0 + warp_n * 32 + ni * 8 + thr * 2;
            *(float2*)&Cg[r0 * E_DIM + col]       = make_float2(acc[mi][ni][0], acc[mi][ni][1]);
            *(float2*)&Cg[(r0 + 8) * E_DIM + col] = make_float2(acc[mi][ni][2], acc[mi][ni][3]);
        }
    }
}

// ===========================================================================
// Fused RoPE + KV cache scatter (R16 component — measured faster than split).
// ===========================================================================
__global__ void rope_cache_kernel(float* __restrict__ qkv,
                                  const float* __restrict__ cosv,
                                  const float* __restrict__ sinv,
                                  const int* __restrict__ block_tables,
                                  float* __restrict__ out_k,
                                  float* __restrict__ out_v)
{
    long long idx = (long long)blockIdx.x * blockDim.x + threadIdx.x;
    if (idx >= (long long)T_TOK * H_NUM * 64) return;
    int j = idx & 63;
    int h = (idx >> 6) & (H_NUM - 1);
    long long t = idx >> 11;

    float c = cosv[t * 64 + j];
    float s = sinv[t * 64 + j];

    // rope q in place
    float* qp = g_qkv + t * E_DIM + h * D_HEAD;
    float q1 = qp[j], q2 = qp[j + 64];
    qp[j]      = q1 * c - q2 * s;
    qp[j + 64] = q2 * c + q1 * s;

    // rope k in place + scatter
    float* kp = g_qkv + (long long)T_TOK * E_DIM + t * E_DIM + h * D_HEAD;
    float k1 = kp[j], k2 = kp[j + 64];
    float kr1 = k1 * c - k2 * s;
    float kr2 = k2 * c + k1 * s;
    kp[j]      = kr1;
    kp[j + 64] = kr2;

    int b  = (int)(t >> 10);
    int nb = (int)((t >> 4) & 63);
    int bs = (int)(t & 15);
    int blk = block_tables[b * NB_BLK + nb];
    long long cdst = (((long long)blk * H_NUM + h) * BS_BLK + bs) * D_HEAD;
    out_k[cdst + j]      = kr1;
    out_k[cdst + j + 64] = kr2;

    // v scatter (no rope)
    const float* vp = g_qkv + 2LL * T_TOK * E_DIM + t * E_DIM + h * D_HEAD;
    out_v[cdst + j]      = vp[j];
    out_v[cdst + j + 64] = vp[j + 64];
}

// ===========================================================================
// Flash attention, fp32 with packed f32x2 FMA, causal.
// Writes hi/lo half planes for the O-proj GEMM. (R13 version, unchanged.)
// ===========================================================================
#define QS_STRIDE 130
#define KS_STRIDE 130
#define VS_STRIDE 132
#define PS_STRIDE 65

__global__ __launch_bounds__(256, 1)
void attn_kernel(const float* __restrict__ qkv,
                 __half* __restrict__ ohi, __half* __restrict__ olo)
{
    extern __shared__ float smf[];
    float* Qs = smf;
    float* Ks = Qs + 64 * QS_STRIDE;
    float* Vs = Ks + 64 * KS_STRIDE;
    float* Ps = Vs + 64 * VS_STRIDE;
    float* alpha_sh = Ps + 64 * PS_STRIDE;
    float* l_sh = alpha_sh + 64;

    int tid = threadIdx.x;
    int tx = tid & 15, ty = tid >> 4;
    int qt = blockIdx.x, h = blockIdx.y, b = blockIdx.z;
    int q0 = qt * 64;

    const long long TE = (long long)T_TOK * E_DIM;
    const float* qbase = qkv;
    const float* kbase = qkv + TE;
    const float* vbase = qkv + 2 * TE;
    const float scale = 0.08838834764831845f;

    for (int c = tid; c < 64 * 32; c += 256) {
        int row = c >> 5;
        int c4 = (c & 31) * 4;
        float4 v = *(const float4*)&qbase[((long long)(b * S_LEN + q0 + row)) * E_DIM + h * D_HEAD + c4];
        *(float2*)&Qs[row * QS_STRIDE + c4]     = make_float2(v.x, v.y);
        *(float2*)&Qs[row * QS_STRIDE + c4 + 2] = make_float2(v.z, v.w);
    }

    float m_r = -1e30f, l_r = 0.f;
    uint64_t o2[4][4];
    #pragma unroll
    for (int i = 0; i < 4; i++)
        #pragma unroll
        for (int j = 0; j < 4; j++) o2[i][j] = 0ull;

    int nkt = qt + 1;
    for (int kt = 0; kt < nkt; kt++) {
        int k0 = kt * 64;
        __syncthreads();
        for (int c = tid; c < 64 * 32; c += 256) {
            int row = c >> 5;
            int c4 = (c & 31) * 4;
            long long goff = ((long long)(b * S_LEN + k0 + row)) * E_DIM + h * D_HEAD + c4;
            float4 kv = *(const float4*)&kbase[goff];
            *(float2*)&Ks[row * KS_STRIDE + c4]     = make_float2(kv.x, kv.y);
            *(float2*)&Ks[row * KS_STRIDE + c4 + 2] = make_float2(kv.z, kv.w);
            float4 vv = *(const float4*)&vbase[goff];
            *(float4*)&Vs[row * VS_STRIDE + c4] = vv;
        }
        __syncthreads();

        uint64_t s2[4][4];
        #pragma unroll
        for (int i = 0; i < 4; i++)
            #pragma unroll
            for (int j = 0; j < 4; j++) s2[i][j] = 0ull;
        const float* qr0 = &Qs[(ty +  0) * QS_STRIDE];
        const float* qr1 = &Qs[(ty + 16) * QS_STRIDE];
        const float* qr2 = &Qs[(ty + 32) * QS_STRIDE];
        const float* qr3 = &Qs[(ty + 48) * QS_STRIDE];
        const float* kr0 = &Ks[(tx +  0) * KS_STRIDE];
        const float* kr1 = &Ks[(tx + 16) * KS_STRIDE];
        const float* kr2 = &Ks[(tx + 32) * KS_STRIDE];
        const float* kr3 = &Ks[(tx + 48) * KS_STRIDE];
        #pragma unroll 4
        for (int d = 0; d < 128; d += 2) {
            uint64_t a0 = *(const uint64_t*)(qr0 + d);
            uint64_t a1 = *(const uint64_t*)(qr1 + d);
            uint64_t a2 = *(const uint64_t*)(qr2 + d);
            uint64_t a3 = *(const uint64_t*)(qr3 + d);
            uint64_t b0 = *(const uint64_t*)(kr0 + d);
            uint64_t b1 = *(const uint64_t*)(kr1 + d);
            uint64_t b2 = *(const uint64_t*)(kr2 + d);
            uint64_t b3 = *(const uint64_t*)(kr3 + d);
            FMA2(s2[0][0], a0, b0); FMA2(s2[0][1], a0, b1); FMA2(s2[0][2], a0, b2); FMA2(s2[0][3], a0, b3);
            FMA2(s2[1][0], a1, b0); FMA2(s2[1][1], a1, b1); FMA2(s2[1][2], a1, b2); FMA2(s2[1][3], a1, b3);
            FMA2(s2[2][0], a2, b0); FMA2(s2[2][1], a2, b1); FMA2(s2[2][2], a2, b2); FMA2(s2[2][3], a2, b3);
            FMA2(s2[3][0], a3, b0); FMA2(s2[3][1], a3, b1); FMA2(s2[3][2], a3, b2); FMA2(s2[3][3], a3, b3);
        }
        bool diag = (kt == qt);
        #pragma unroll
        for (int i = 0; i < 4; i++) {
            int qi = ty + 16 * i;
            #pragma unroll
            for (int j = 0; j < 4; j++) {
                int ki = tx + 16 * j;
                float lo, hi;
                UNPACK2(lo, hi, s2[i][j]);
                float val = (lo + hi) * scale;
                if (diag && ki > qi) val = -1e30f;
                Ps[qi * PS_STRIDE + ki] = val;
            }
        }
        __syncthreads();

        {
            int q = tid >> 2;
            int cc = (tid & 3) * 16;
            float* pr = &Ps[q * PS_STRIDE + cc];
            float mx = -1e30f;
            #pragma unroll
            for (int c = 0; c < 16; c++) mx = fmaxf(mx, pr[c]);
            mx = fmaxf(mx, __shfl_xor_sync(0xffffffffu, mx, 1));
            mx = fmaxf(mx, __shfl_xor_sync(0xffffffffu, mx, 2));
            float m_new = fmaxf(m_r, mx);
            float al = __expf(m_r - m_new);
            float sum = 0.f;
            #pragma unroll
            for (int c = 0; c < 16; c++) {
                float p = __expf(pr[c] - m_new);
                pr[c] = p;
                sum += p;
            }
            sum += __shfl_xor_sync(0xffffffffu, sum, 1);
            sum += __shfl_xor_sync(0xffffffffu, sum, 2);
            l_r = l_r * al + sum;
            m_r = m_new;
            if ((tid & 3) == 0) { alpha_sh[q] = al; l_sh[q] = l_r; }
        }
        __syncthreads();

        #pragma unroll
        for (int i = 0; i < 4; i++) {
            float av = alpha_sh[ty + 16 * i];
            uint64_t avp; PACK2(avp, av, av);
            #pragma unroll
            for (int j = 0; j < 4; j++) { uint64_t t; MUL2(t, o2[i][j], avp); o2[i][j] = t; }
        }

        #pragma unroll 2
        for (int k = 0; k < 64; k++) {
            float p0 = Ps[(ty +  0) * PS_STRIDE + k];
            float p1 = Ps[(ty + 16) * PS_STRIDE + k];
            float p2 = Ps[(ty + 32) * PS_STRIDE + k];
            float p3 = Ps[(ty + 48) * PS_STRIDE + k];
            uint64_t pp0, pp1, pp2, pp3;
            PACK2(pp0, p0, p0); PACK2(pp1, p1, p1);
            PACK2(pp2, p2, p2); PACK2(pp3, p3, p3);
            float4 v0 = *(float4*)&Vs[k * VS_STRIDE + tx * 8];
            float4 v1 = *(float4*)&Vs[k * VS_STRIDE + tx * 8 + 4];
            uint64_t vv0, vv1, vv2, vv3;
            PACK2(vv0, v0.x, v0.y); PACK2(vv1, v0.z, v0.w);
            PACK2(vv2, v1.x, v1.y); PACK2(vv3, v1.z, v1.w);
            FMA2(o2[0][0], pp0, vv0); FMA2(o2[0][1], pp0, vv1); FMA2(o2[0][2], pp0, vv2); FMA2(o2[0][3], pp0, vv3);
            FMA2(o2[1][0], pp1, vv0); FMA2(o2[1][1], pp1, vv1); FMA2(o2[1][2], pp1, vv2); FMA2(o2[1][3], pp1, vv3);
            FMA2(o2[2][0], pp2, vv0); FMA2(o2[2][1], pp2, vv1); FMA2(o2[2][2], pp2, vv2); FMA2(o2[2][3], pp2, vv3);
            FMA2(o2[3][0], pp3, vv0); FMA2(o2[3][1], pp3, vv1); FMA2(o2[3][2], pp3, vv2); FMA2(o2[3][3], pp3, vv3);
        }
    }

    #pragma unroll
    for (int i = 0; i < 4; i++) {
        int qi = ty + 16 * i;
        float inv = 1.f / l_sh[qi];
        long long off = ((long long)(b * S_LEN + q0 + qi)) * E_DIM + h * D_HEAD + tx * 8;
        #pragma unroll
        for (int jp = 0; jp < 4; jp++) {
            float e0, e1;
            UNPACK2(e0, e1, o2[i][jp]);
            float v0 = e0 * inv;
            float v1 = e1 * inv;
            __half h0 = __float2half_rn(v0), h1 = __float2half_rn(v1);
            __half l0 = __float2half_rn(v0 - __half2float(h0));
            __half l1 = __float2half_rn(v1 - __half2float(h1));
            *(half2*)&ohi[off + jp * 2] = __halves2half2(h0, h1);
            *(half2*)&olo[off + jp * 2] = __halves2half2(l0, l1);
        }
    }
}

// ===========================================================================
extern "C" void kernel_launch(void* const* d_in, const int* in_sizes, int n_in,
                              void* d_out, int out_size)
{
    const float* hidden   = (const float*)d_in[0];
    const float* qkv_w    = (const float*)d_in[1];
    const float* o_w      = (const float*)d_in[2];
    const float* cosv     = (const float*)d_in[3];
    const float* sinv     = (const float*)d_in[4];
    const int*   blk_tab  = (const int*)d_in[7];

    float* out   = (float*)d_out;
    float* out_k = out + (size_t)T_TOK * E_DIM;
    float* out_v = out_k + (size_t)T_TOK * E_DIM;

    float*  qkv;  cudaGetSymbolAddress((void**)&qkv,  g_qkv);
    __half* wth;  cudaGetSymbolAddress((void**)&wth,  g_wt_hi);
    __half* wtl;  cudaGetSymbolAddress((void**)&wtl,  g_wt_lo);
    __half* ahi;  cudaGetSymbolAddress((void**)&ahi,  g_ahi);
    __half* alo;  cudaGetSymbolAddress((void**)&alo,  g_alo);

    // 0a) Transpose + split weights
    transpose_split_kernel<<<dim3(E_DIM / 32, E_DIM / 32, 4), dim3(32, 8)>>>(qkv_w, o_w, wth, wtl);
    // 0b) Split hidden activations
    {
        long long total = (long long)T_TOK * E_DIM / 4;
        split_a_kernel<<<(unsigned)((total + 255) / 256), 256>>>(hidden, ahi, alo);
    }

    // 1) QKV projection (fp16 split mma + ldmatrix, 2-stage, occ 2 — R13 config)
    cudaFuncSetAttribute(gemm_mma_kernel, cudaFuncAttributeMaxDynamicSharedMemorySize, GEMM_SMEM);
    gemm_mma_kernel<<<dim3(E_DIM / 128, T_TOK / 128, 3), 256, GEMM_SMEM>>>(
        ahi, alo, wth, wtl, qkv, (long long)E_DIM * E_DIM, (long long)T_TOK * E_DIM);

    // 2) Fused RoPE + KV cache scatter
    {
        long long total = (long long)T_TOK * H_NUM * 64;
        rope_cache_kernel<<<(unsigned)((total + 255) / 256), 256>>>(
            qkv, cosv, sinv, blk_tab, out_k, out_v);
    }

    // 3) Flash attention (packed f32x2, hi/lo half output)
    {
        int smem = (64 * QS_STRIDE + 64 * KS_STRIDE + 64 * VS_STRIDE +
                    64 * PS_STRIDE + 64 + 64) * (int)sizeof(float);
        cudaFuncSetAttribute(attn_kernel, cudaFuncAttributeMaxDynamicSharedMemorySize, smem);
        attn_kernel<<<dim3(S_LEN / 64, H_NUM, B_SZ), 256, smem>>>(qkv, ahi, alo);
    }

    // 4) Output projection
    gemm_mma_kernel<<<dim3(E_DIM / 128, T_TOK / 128, 1), 256, GEMM_SMEM>>>(
        ahi, alo, wth + 3ULL * E_DIM * E_DIM, wtl + 3ULL * E_DIM * E_DIM, out, 0, 0);
}